// round 7
// baseline (speedup 1.0000x reference)
#include <cuda_runtime.h>
#include <cuda_fp16.h>
#include <stdint.h>
#include <math.h>

// Problem dims (fixed)
#define B_ 256
#define S_ 256
#define I_ 3
#define H_ 1024
#define T_ 64
#define BH (B_*H_)

#define BM 32
#define BN 64
#define BK 64
#define KCH 16
#define NCTA 128
#define STAGE_H 12288                    // halves per pipeline stage
#define SMEM_HALVES (KCH*BN*BK + 3*STAGE_H)   // 65536 + 36864 = 102400
#define SMEM_BYTES (SMEM_HALVES*2)            // 204800 B

// ---------------------------------------------------------------------------
// Device scratch (no allocation allowed)
// ---------------------------------------------------------------------------
__device__ __half g_ys0_hi[S_*BH];
__device__ __half g_ys0_lo[S_*BH];
__device__ __half g_h1hi[2*BH], g_h1lo[2*BH];
__device__ __half g_hAhi[2*BH], g_hAlo[2*BH];
__device__ __half g_hBhi[2*BH], g_hBlo[2*BH];
__device__ __half g_zb[BH];
__device__ float  g_inp[B_*I_];
// 0:eWhh0 1:eWih1 2:eWhh1 3:dWhh0 4:dWih1 5:dWhh1
__device__ __half g_W[6][H_*H_];
__device__ unsigned g_cnt, g_gen;

// ---------------------------------------------------------------------------
__global__ void k_init(const float* __restrict__ x) {
    int i = blockIdx.x * blockDim.x + threadIdx.x;
    if (i == 0) { g_cnt = 0; g_gen = 0; }
    if (i < BH) g_zb[i] = __float2half(0.0f);
    if (i < B_*I_) {
        int b = i / I_, c = i % I_;
        g_inp[i] = x[b*(S_*I_) + (S_-1)*I_ + c];
    }
}

__global__ void k_conv6(const float* __restrict__ s0, const float* __restrict__ s1,
                        const float* __restrict__ s2, const float* __restrict__ s3,
                        const float* __restrict__ s4, const float* __restrict__ s5) {
    int i = blockIdx.x * blockDim.x + threadIdx.x;
    const float* srcs[6] = {s0, s1, s2, s3, s4, s5};
    int j = blockIdx.y;
    g_W[j][i] = __float2half(srcs[j][i]);
}

// ---------------------------------------------------------------------------
// Grid barrier: all NCTA CTAs resident (1 CTA/SM by smem). Cumulative fences
// give device-wide visibility of pre-barrier writes to post-barrier reads.
// ---------------------------------------------------------------------------
__device__ __forceinline__ void gridbar(int tid) {
    __syncthreads();
    if (tid == 0) {
        __threadfence();
        unsigned gen = *(volatile unsigned*)&g_gen;
        unsigned a = atomicAdd(&g_cnt, 1);
        if (a == NCTA-1) {
            g_cnt = 0;
            __threadfence();
            atomicAdd(&g_gen, 1);
        } else {
            while (*(volatile unsigned*)&g_gen == gen) { }
        }
        __threadfence();
    }
    __syncthreads();
}

#define CP16(dst_sm, src_gm) \
    asm volatile("cp.async.cg.shared.global [%0], [%1], 16;\n" \
                 :: "r"(dst_sm), "l"(src_gm))

// Load this CTA's 64x1024 W slice (swizzled chunk tiles) into smem cache.
__device__ void loadWc(const __half* __restrict__ W, __half* Wc, int bn0, int tid) {
    const int lrow = tid >> 3, lcolh = (tid & 7) * 8;
    for (int kc = 0; kc < KCH; ++kc) {
        #pragma unroll
        for (int i = 0; i < 4; ++i) {
            int r  = lrow + 16*i;
            int sc = lcolh ^ ((r & 7) * 8);
            uint32_t d = (uint32_t)__cvta_generic_to_shared(Wc + kc*(BN*BK) + r*64 + sc);
            CP16(d, W + (size_t)(bn0 + r)*H_ + kc*64 + lcolh);
        }
    }
    asm volatile("cp.async.commit_group;");
    asm volatile("cp.async.wait_group 0;");
    __syncthreads();
}

// ldmatrix helpers (tile row width 64 halves, XOR swizzle on 8-half granule)
__device__ __forceinline__ void lda(uint32_t a[2][4], const __half* base, int kh, int lane) {
    #pragma unroll
    for (int h = 0; h < 2; ++h) {
        int r  = h*16 + (lane & 15);
        int cc = (kh + ((lane >> 4) * 8)) ^ ((r & 7) * 8);
        uint32_t addr = (uint32_t)__cvta_generic_to_shared(base + r*64 + cc);
        asm volatile("ldmatrix.sync.aligned.m8n8.x4.shared.b16 {%0,%1,%2,%3}, [%4];"
            : "=r"(a[h][0]), "=r"(a[h][1]), "=r"(a[h][2]), "=r"(a[h][3]) : "r"(addr));
    }
}
__device__ __forceinline__ void ldb(uint32_t b[4], const __half* base, int kh, int lane, int w) {
    int j  = lane >> 3;
    int r  = w*16 + ((j >> 1) * 8) + (lane & 7);
    int cc = (kh + (j & 1) * 8) ^ ((r & 7) * 8);
    uint32_t addr = (uint32_t)__cvta_generic_to_shared(base + r*64 + cc);
    asm volatile("ldmatrix.sync.aligned.m8n8.x4.shared.b16 {%0,%1,%2,%3}, [%4];"
        : "=r"(b[0]), "=r"(b[1]), "=r"(b[2]), "=r"(b[3]) : "r"(addr));
}
__device__ __forceinline__ void mma4(float acc[2][2][4], const uint32_t a[2][4], const uint32_t b[4]) {
    #pragma unroll
    for (int mi = 0; mi < 2; ++mi)
        #pragma unroll
        for (int ni = 0; ni < 2; ++ni)
            asm volatile(
                "mma.sync.aligned.m16n8k16.row.col.f32.f16.f16.f32 "
                "{%0,%1,%2,%3}, {%4,%5,%6,%7}, {%8,%9}, {%0,%1,%2,%3};"
                : "+f"(acc[mi][ni][0]), "+f"(acc[mi][ni][1]),
                  "+f"(acc[mi][ni][2]), "+f"(acc[mi][ni][3])
                : "r"(a[mi][0]), "r"(a[mi][1]), "r"(a[mi][2]), "r"(a[mi][3]),
                  "r"(b[2*ni]), "r"(b[2*ni+1]));
}

// ---------------------------------------------------------------------------
// One RNN step GEMM (this CTA's 32x64 output tile).
// MODE 0: C = A*Wc          (W cached in smem)
// MODE 1: C = A*Wst         (W streamed)
// MODE 2: C = A*Wst + A2*Wc
// A given as fp16 (hi, lo); both products vs same W. Epilogue: +xs.Wsm +b1+b2,
// tanh, write fp16 hi/lo.
// ---------------------------------------------------------------------------
template<int MODE>
__device__ void do_step(
    const __half* __restrict__ Ahi, const __half* __restrict__ Alo,
    const __half* __restrict__ A2hi, const __half* __restrict__ A2lo,
    const __half* __restrict__ Wst,
    const __half* Wc, __half* stages,
    const float* __restrict__ xs, int xs_stride, const float* __restrict__ Wsm,
    const float* __restrict__ b1, const float* __restrict__ b2,
    __half* __restrict__ Chi, __half* __restrict__ Clo,
    int bm0, int bn0, int tid)
{
    const int lane = tid & 31, w = tid >> 5;
    const int lrow = tid >> 3, lcolh = (tid & 7) * 8;

    auto pf = [&](int c, int slot) {
        __half* st = stages + slot*STAGE_H;
        int k0 = c*BK;
        #pragma unroll
        for (int i = 0; i < 2; ++i) {
            int r  = lrow + 16*i;
            int sc = lcolh ^ ((r & 7) * 8);
            uint32_t d;
            d = (uint32_t)__cvta_generic_to_shared(st + r*64 + sc);
            CP16(d, Ahi + (size_t)(bm0 + r)*H_ + k0 + lcolh);
            d = (uint32_t)__cvta_generic_to_shared(st + 2048 + r*64 + sc);
            CP16(d, Alo + (size_t)(bm0 + r)*H_ + k0 + lcolh);
            if (MODE == 2) {
                d = (uint32_t)__cvta_generic_to_shared(st + 4096 + r*64 + sc);
                CP16(d, A2hi + (size_t)(bm0 + r)*H_ + k0 + lcolh);
                d = (uint32_t)__cvta_generic_to_shared(st + 6144 + r*64 + sc);
                CP16(d, A2lo + (size_t)(bm0 + r)*H_ + k0 + lcolh);
            }
        }
        if (MODE >= 1) {
            #pragma unroll
            for (int i = 0; i < 4; ++i) {
                int r  = lrow + 16*i;
                int sc = lcolh ^ ((r & 7) * 8);
                uint32_t d = (uint32_t)__cvta_generic_to_shared(st + 8192 + r*64 + sc);
                CP16(d, Wst + (size_t)(bn0 + r)*H_ + k0 + lcolh);
            }
        }
    };

    float acc[2][2][4];
    #pragma unroll
    for (int mi = 0; mi < 2; ++mi)
        #pragma unroll
        for (int ni = 0; ni < 2; ++ni)
            #pragma unroll
            for (int q = 0; q < 4; ++q) acc[mi][ni][q] = 0.0f;

    pf(0, 0); asm volatile("cp.async.commit_group;");
    pf(1, 1); asm volatile("cp.async.commit_group;");

    for (int c = 0; c < KCH; ++c) {
        asm volatile("cp.async.wait_group 1;");
        __syncthreads();
        if (c + 2 < KCH) pf(c + 2, (c + 2) % 3);
        asm volatile("cp.async.commit_group;");

        const __half* st = stages + (c % 3)*STAGE_H;
        #pragma unroll
        for (int k16 = 0; k16 < 4; ++k16) {
            const int kh = 16*k16;
            uint32_t ahi[2][4], alo[2][4];
            lda(ahi, st, kh, lane);
            lda(alo, st + 2048, kh, lane);
            uint32_t bs[4], bc[4];
            if (MODE >= 1) ldb(bs, st + 8192, kh, lane, w);
            if (MODE != 1) ldb(bc, Wc + c*(BN*BK), kh, lane, w);
            if (MODE == 0) { mma4(acc, ahi, bc); mma4(acc, alo, bc); }
            if (MODE == 1) { mma4(acc, ahi, bs); mma4(acc, alo, bs); }
            if (MODE == 2) {
                mma4(acc, ahi, bs); mma4(acc, alo, bs);
                uint32_t a2hi[2][4], a2lo[2][4];
                lda(a2hi, st + 4096, kh, lane);
                lda(a2lo, st + 6144, kh, lane);
                mma4(acc, a2hi, bc); mma4(acc, a2lo, bc);
            }
        }
    }

    // Epilogue
    #pragma unroll
    for (int mi = 0; mi < 2; ++mi) {
        #pragma unroll
        for (int h = 0; h < 2; ++h) {
            const int row = bm0 + mi*16 + (lane >> 2) + h*8;
            float x0 = 0.f, x1 = 0.f, x2 = 0.f;
            if (xs) {
                const float* xr = xs + (size_t)row * xs_stride;
                x0 = xr[0]; x1 = xr[1]; x2 = xr[2];
            }
            #pragma unroll
            for (int ni = 0; ni < 2; ++ni) {
                const int col = bn0 + w*16 + ni*8 + (lane & 3)*2;
                float v0 = acc[mi][ni][h*2 + 0];
                float v1 = acc[mi][ni][h*2 + 1];
                if (xs) {
                    v0 += x0*Wsm[col*3+0] + x1*Wsm[col*3+1] + x2*Wsm[col*3+2];
                    v1 += x0*Wsm[(col+1)*3+0] + x1*Wsm[(col+1)*3+1] + x2*Wsm[(col+1)*3+2];
                }
                v0 += b1[col] + b2[col];
                v1 += b1[col+1] + b2[col+1];
                v0 = tanhf(v0); v1 = tanhf(v1);
                const size_t off = (size_t)row*H_ + col;
                __half h0 = __float2half(v0);
                __half h1 = __float2half(v1);
                __half l0 = __float2half(v0 - __half2float(h0));
                __half l1 = __float2half(v1 - __half2float(h1));
                *(__half2*)(Chi + off) = __halves2half2(h0, h1);
                *(__half2*)(Clo + off) = __halves2half2(l0, l1);
            }
        }
    }
}

// ---------------------------------------------------------------------------
// Persistent whole-network kernel. 128 CTAs x 128 threads, 1 CTA/SM.
// ---------------------------------------------------------------------------
__global__ __launch_bounds__(128) void k_persist(
    const float* __restrict__ x,
    const float* __restrict__ eWih0, const float* __restrict__ ebih0, const float* __restrict__ ebhh0,
    const float* __restrict__ ebih1, const float* __restrict__ ebhh1,
    const float* __restrict__ dWih0, const float* __restrict__ dbih0, const float* __restrict__ dbhh0,
    const float* __restrict__ dbih1, const float* __restrict__ dbhh1,
    const float* __restrict__ dWlin, const float* __restrict__ dblin,
    float* __restrict__ out)
{
    extern __shared__ __half sm[];
    __half* Wc     = sm;
    __half* stages = sm + KCH*BN*BK;
    const int tid = threadIdx.x;
    const int bid = blockIdx.x;
    const int bn0 = (bid & 15) * BN;
    const int bm0 = (bid >> 4) * BM;

    // ---- Phase 1: encoder layer 0 (W = eWhh0 cached) ----
    loadWc(g_W[0], Wc, bn0, tid);
    gridbar(tid);
    for (int t = 0; t < S_; ++t) {
        const __half* Ah = t ? g_ys0_hi + (size_t)(t-1)*BH : g_zb;
        const __half* Al = t ? g_ys0_lo + (size_t)(t-1)*BH : g_zb;
        do_step<0>(Ah, Al, nullptr, nullptr, nullptr, Wc, stages,
                   x + t*I_, S_*I_, eWih0, ebih0, ebhh0,
                   g_ys0_hi + (size_t)t*BH, g_ys0_lo + (size_t)t*BH,
                   bm0, bn0, tid);
        gridbar(tid);
    }

    // ---- Phase 2: encoder layer 1, fused input+recurrent (Wc = eWhh1) ----
    loadWc(g_W[2], Wc, bn0, tid);
    gridbar(tid);
    for (int t = 0; t < S_; ++t) {
        const __half* A2h = t ? g_h1hi + ((t-1)&1)*BH : g_zb;
        const __half* A2l = t ? g_h1lo + ((t-1)&1)*BH : g_zb;
        do_step<2>(g_ys0_hi + (size_t)t*BH, g_ys0_lo + (size_t)t*BH, A2h, A2l,
                   g_W[1], Wc, stages,
                   nullptr, 0, nullptr, ebih1, ebhh1,
                   g_h1hi + (t&1)*BH, g_h1lo + (t&1)*BH,
                   bm0, bn0, tid);
        gridbar(tid);
    }

    // ---- Phase 3: decoder (Wc = dWhh1 cached for hB steps) ----
    loadWc(g_W[5], Wc, bn0, tid);
    gridbar(tid);
    const __half* pAh = g_ys0_hi + (size_t)(S_-1)*BH;
    const __half* pAl = g_ys0_lo + (size_t)(S_-1)*BH;
    const __half* pBh = g_h1hi + ((S_-1)&1)*BH;
    const __half* pBl = g_h1lo + ((S_-1)&1)*BH;
    for (int t = 0; t < T_; ++t) {
        __half* nAh = g_hAhi + (t&1)*BH;
        __half* nAl = g_hAlo + (t&1)*BH;
        do_step<1>(pAh, pAl, nullptr, nullptr, g_W[3], nullptr, stages,
                   g_inp, I_, dWih0, dbih0, dbhh0,
                   nAh, nAl, bm0, bn0, tid);
        gridbar(tid);
        __half* nBh = g_hBhi + (t&1)*BH;
        __half* nBl = g_hBlo + (t&1)*BH;
        do_step<2>(nAh, nAl, pBh, pBl, g_W[4], Wc, stages,
                   nullptr, 0, nullptr, dbih1, dbhh1,
                   nBh, nBl, bm0, bn0, tid);
        gridbar(tid);
        // decout: 256 warps (CTAs 0..63), one batch row each
        if (bid < 64) {
            const int row  = bid*4 + (tid >> 5);
            const int lane = tid & 31;
            const __half* hh = nBh + (size_t)row*H_;
            const __half* hl = nBl + (size_t)row*H_;
            float s = 0.0f;
            #pragma unroll 8
            for (int k = lane; k < H_; k += 32)
                s = fmaf(__half2float(hh[k]) + __half2float(hl[k]), dWlin[k], s);
            #pragma unroll
            for (int o = 16; o > 0; o >>= 1)
                s += __shfl_xor_sync(0xffffffffu, s, o);
            if (lane == 0) {
                const float o_ = s + dblin[0];
                out[row*T_ + t] = o_;
                const float i0 = g_inp[row*3 + 0];
                const float i1 = g_inp[row*3 + 1];
                const float c0 = o_;
                const float c1 = i0 - c0;
                const float c2 = i1 - c1;
                g_inp[row*3 + 0] = c0;
                g_inp[row*3 + 1] = c1;
                g_inp[row*3 + 2] = c2;
            }
        }
        gridbar(tid);
        pAh = nAh; pAl = nAl; pBh = nBh; pBl = nBl;
    }
}

// ---------------------------------------------------------------------------
// Orchestration: 3 launches, all on default stream (graph-capturable).
// ---------------------------------------------------------------------------
extern "C" void kernel_launch(void* const* d_in, const int* in_sizes, int n_in,
                              void* d_out, int out_size)
{
    (void)in_sizes; (void)n_in; (void)out_size;
    const float* x     = (const float*)d_in[0];
    const float* eWih0 = (const float*)d_in[2];
    const float* eWhh0 = (const float*)d_in[3];
    const float* ebih0 = (const float*)d_in[4];
    const float* ebhh0 = (const float*)d_in[5];
    const float* eWih1 = (const float*)d_in[6];
    const float* eWhh1 = (const float*)d_in[7];
    const float* ebih1 = (const float*)d_in[8];
    const float* ebhh1 = (const float*)d_in[9];
    const float* dWih0 = (const float*)d_in[10];
    const float* dWhh0 = (const float*)d_in[11];
    const float* dbih0 = (const float*)d_in[12];
    const float* dbhh0 = (const float*)d_in[13];
    const float* dWih1 = (const float*)d_in[14];
    const float* dWhh1 = (const float*)d_in[15];
    const float* dbih1 = (const float*)d_in[16];
    const float* dbhh1 = (const float*)d_in[17];
    const float* dWlin = (const float*)d_in[18];
    const float* dblin = (const float*)d_in[19];
    float* out = (float*)d_out;

    static bool s_attr = false;
    if (!s_attr) {
        cudaFuncSetAttribute(k_persist,
                             cudaFuncAttributeMaxDynamicSharedMemorySize, SMEM_BYTES);
        s_attr = true;
    }

    k_init<<<(BH + 255)/256, 256>>>(x);
    // order: eWhh0, eWih1, eWhh1, dWhh0, dWih1, dWhh1
    k_conv6<<<dim3(H_*H_/256, 6), 256>>>(eWhh0, eWih1, eWhh1, dWhh0, dWih1, dWhh1);
    k_persist<<<NCTA, 128, SMEM_BYTES>>>(x,
        eWih0, ebih0, ebhh0, ebih1, ebhh1,
        dWih0, dbih0, dbhh0, dbih1, dbhh1,
        dWlin, dblin, out);
}

// round 8
// speedup vs baseline: 1.1894x; 1.1894x over previous
#include <cuda_runtime.h>
#include <cuda_fp16.h>
#include <stdint.h>
#include <math.h>

// Problem dims (fixed)
#define B_ 256
#define S_ 256
#define I_ 3
#define H_ 1024
#define T_ 64
#define BH (B_*H_)

#define BM 32
#define BN 64
#define BK 64
#define KCH 16
#define NCTA 128
#define THREADS 256

// Shared stage layout (halves). One stage holds all tiles for one k-chunk.
#define O_YH 0
#define O_YL 2048
#define O_HH 4096
#define O_HL 6144
#define O_W0 8192
#define O_W1 12288
#define O_W2 16384
#define SSTR 20480
#define SMEM_BYTES (3*SSTR*2)   // 122880

// ---------------------------------------------------------------------------
// Device scratch (no allocation allowed)
// ---------------------------------------------------------------------------
__device__ __half g_ys0_hi[S_*BH];
__device__ __half g_ys0_lo[S_*BH];
__device__ __half g_h1hi[2*BH], g_h1lo[2*BH];
__device__ __half g_hAhi[2*BH], g_hAlo[2*BH];
__device__ __half g_hBhi[2*BH], g_hBlo[2*BH];
__device__ __half g_zb[BH];
__device__ float  g_inp[B_*I_];
// 0:eWhh0 1:eWih1 2:eWhh1 3:dWhh0 4:dWih1 5:dWhh1
__device__ __half g_W[6][H_*H_];
__device__ unsigned g_cnt, g_gen;

// ---------------------------------------------------------------------------
__global__ void k_init(const float* __restrict__ x) {
    int i = blockIdx.x * blockDim.x + threadIdx.x;
    if (i == 0) { g_cnt = 0; g_gen = 0; }
    if (i < BH) g_zb[i] = __float2half(0.0f);
    if (i < B_*I_) {
        int b = i / I_, c = i % I_;
        g_inp[i] = x[b*(S_*I_) + (S_-1)*I_ + c];
    }
}

__global__ void k_conv6(const float* __restrict__ s0, const float* __restrict__ s1,
                        const float* __restrict__ s2, const float* __restrict__ s3,
                        const float* __restrict__ s4, const float* __restrict__ s5) {
    int i = blockIdx.x * blockDim.x + threadIdx.x;
    const float* srcs[6] = {s0, s1, s2, s3, s4, s5};
    int j = blockIdx.y;
    g_W[j][i] = __float2half(srcs[j][i]);
}

// ---------------------------------------------------------------------------
// Grid barrier (all NCTA CTAs resident; 1 CTA/SM forced by 120KB smem).
// ---------------------------------------------------------------------------
__device__ __forceinline__ void gridbar(int tid) {
    __syncthreads();
    if (tid == 0) {
        __threadfence();
        unsigned gen = *(volatile unsigned*)&g_gen;
        unsigned a = atomicAdd(&g_cnt, 1);
        if (a == NCTA-1) {
            g_cnt = 0;
            __threadfence();
            atomicAdd(&g_gen, 1);
        } else {
            while (*(volatile unsigned*)&g_gen == gen) { }
        }
        __threadfence();
    }
    __syncthreads();
}

__device__ __forceinline__ uint32_t smaddr(const void* p) {
    return (uint32_t)__cvta_generic_to_shared(p);
}
#define CP16(dst_sm, src_gm) \
    asm volatile("cp.async.cg.shared.global [%0], [%1], 16;\n" \
                 :: "r"(dst_sm), "l"(src_gm))

// ldmatrix A: warp's 16x16 block of a 32x64 swizzled tile (wm selects M-half)
__device__ __forceinline__ void ldaW(uint32_t a[4], const __half* base, int kh, int lane, int wm) {
    int r  = wm*16 + (lane & 15);
    int cc = (kh + ((lane >> 4) * 8)) ^ ((r & 7) * 8);
    uint32_t addr = smaddr(base + r*64 + cc);
    asm volatile("ldmatrix.sync.aligned.m8n8.x4.shared.b16 {%0,%1,%2,%3}, [%4];"
        : "=r"(a[0]), "=r"(a[1]), "=r"(a[2]), "=r"(a[3]) : "r"(addr));
}
// ldmatrix B: warp's n16xk16 block of a 64x64 swizzled W tile (wn selects N group)
__device__ __forceinline__ void ldbW(uint32_t b[4], const __half* base, int kh, int lane, int wn) {
    int j  = lane >> 3;
    int r  = wn*16 + ((j >> 1) * 8) + (lane & 7);
    int cc = (kh + (j & 1) * 8) ^ ((r & 7) * 8);
    uint32_t addr = smaddr(base + r*64 + cc);
    asm volatile("ldmatrix.sync.aligned.m8n8.x4.shared.b16 {%0,%1,%2,%3}, [%4];"
        : "=r"(b[0]), "=r"(b[1]), "=r"(b[2]), "=r"(b[3]) : "r"(addr));
}
__device__ __forceinline__ void mma2(float acc[2][4], const uint32_t a[4], const uint32_t b[4]) {
    #pragma unroll
    for (int ni = 0; ni < 2; ++ni)
        asm volatile(
            "mma.sync.aligned.m16n8k16.row.col.f32.f16.f16.f32 "
            "{%0,%1,%2,%3}, {%4,%5,%6,%7}, {%8,%9}, {%0,%1,%2,%3};"
            : "+f"(acc[ni][0]), "+f"(acc[ni][1]), "+f"(acc[ni][2]), "+f"(acc[ni][3])
            : "r"(a[0]), "r"(a[1]), "r"(a[2]), "r"(a[3]),
              "r"(b[2*ni]), "r"(b[2*ni+1]));
}

// Epilogue: add optional rank-3 x-projection + biases, tanh, write fp16 hi/lo.
__device__ __forceinline__ void epi(
    float acc[2][4],
    const float* __restrict__ xs, int xs_stride, const float* __restrict__ Wsm,
    const float* __restrict__ b1, const float* __restrict__ b2,
    __half* __restrict__ Chi, __half* __restrict__ Clo,
    int bm0, int bn0, int lane, int wm, int wn)
{
    #pragma unroll
    for (int h = 0; h < 2; ++h) {
        const int row = bm0 + wm*16 + (lane >> 2) + h*8;
        float x0 = 0.f, x1 = 0.f, x2 = 0.f;
        if (xs) {
            const float* xr = xs + (size_t)row * xs_stride;
            x0 = xr[0]; x1 = xr[1]; x2 = xr[2];
        }
        #pragma unroll
        for (int ni = 0; ni < 2; ++ni) {
            const int col = bn0 + wn*16 + ni*8 + (lane & 3)*2;
            float v0 = acc[ni][h*2 + 0];
            float v1 = acc[ni][h*2 + 1];
            if (xs) {
                v0 += x0*Wsm[col*3+0] + x1*Wsm[col*3+1] + x2*Wsm[col*3+2];
                v1 += x0*Wsm[(col+1)*3+0] + x1*Wsm[(col+1)*3+1] + x2*Wsm[(col+1)*3+2];
            }
            v0 += b1[col] + b2[col];
            v1 += b1[col+1] + b2[col+1];
            v0 = tanhf(v0); v1 = tanhf(v1);
            const size_t off = (size_t)row*H_ + col;
            __half h0 = __float2half(v0);
            __half h1 = __float2half(v1);
            __half l0 = __float2half(v0 - __half2float(h0));
            __half l1 = __float2half(v1 - __half2float(h1));
            *(__half2*)(Chi + off) = __halves2half2(h0, h1);
            *(__half2*)(Clo + off) = __halves2half2(l0, l1);
        }
    }
}

// ---------------------------------------------------------------------------
// Fused encoder interval t:
//   PART&1: ys0[t]   = tanh(x[t]@Wih0 + ys0[t-1]@Whh0 + b)        (acc0)
//   PART&2: h1[t-1]  = tanh(ys0[t-1]@Wih1 + h1[t-2]@Whh1 + b)     (acc1)
// Both share the A tile ys0[t-1] (hi/lo), loaded once.
// ---------------------------------------------------------------------------
template<int PART>
__device__ void enc_step(int t, const float* __restrict__ x,
    const float* __restrict__ eWih0,
    const float* __restrict__ ebih0, const float* __restrict__ ebhh0,
    const float* __restrict__ ebih1, const float* __restrict__ ebhh1,
    int bm0, int bn0, int tid, __half* sm)
{
    const int lane = tid & 31, wrp = tid >> 5, wm = wrp >> 2, wn = wrp & 3;
    const int lrow = tid >> 3, lcolh = (tid & 7) * 8;

    const __half* Yh = (t >= 1) ? g_ys0_hi + (size_t)(t-1)*BH : g_zb;
    const __half* Yl = (t >= 1) ? g_ys0_lo + (size_t)(t-1)*BH : g_zb;
    const __half* Hh = (t >= 2) ? g_h1hi + (size_t)((t-2)&1)*BH : g_zb;
    const __half* Hl = (t >= 2) ? g_h1lo + (size_t)((t-2)&1)*BH : g_zb;

    auto pf = [&](int c, int slot) {
        __half* st = sm + slot*SSTR;
        const int k0 = c*BK;
        const int r  = lrow;                    // 0..31
        const int sc = lcolh ^ ((r & 7) * 8);
        uint32_t d;
        d = smaddr(st + O_YH + r*64 + sc); CP16(d, Yh + (size_t)(bm0 + r)*H_ + k0 + lcolh);
        d = smaddr(st + O_YL + r*64 + sc); CP16(d, Yl + (size_t)(bm0 + r)*H_ + k0 + lcolh);
        if (PART & 2) {
            d = smaddr(st + O_HH + r*64 + sc); CP16(d, Hh + (size_t)(bm0 + r)*H_ + k0 + lcolh);
            d = smaddr(st + O_HL + r*64 + sc); CP16(d, Hl + (size_t)(bm0 + r)*H_ + k0 + lcolh);
        }
        #pragma unroll
        for (int i = 0; i < 2; ++i) {
            const int r2  = lrow + 32*i;        // 0..63
            const int sc2 = lcolh ^ ((r2 & 7) * 8);
            if (PART & 1) {
                d = smaddr(st + O_W0 + r2*64 + sc2);
                CP16(d, g_W[0] + (size_t)(bn0 + r2)*H_ + k0 + lcolh);
            }
            if (PART & 2) {
                d = smaddr(st + O_W1 + r2*64 + sc2);
                CP16(d, g_W[1] + (size_t)(bn0 + r2)*H_ + k0 + lcolh);
                d = smaddr(st + O_W2 + r2*64 + sc2);
                CP16(d, g_W[2] + (size_t)(bn0 + r2)*H_ + k0 + lcolh);
            }
        }
    };

    float acc0[2][4] = {}, acc1[2][4] = {};

    pf(0, 0); asm volatile("cp.async.commit_group;");
    pf(1, 1); asm volatile("cp.async.commit_group;");

    for (int c = 0; c < KCH; ++c) {
        asm volatile("cp.async.wait_group 1;");
        __syncthreads();
        if (c + 2 < KCH) pf(c + 2, (c + 2) % 3);
        asm volatile("cp.async.commit_group;");

        const __half* st = sm + (c % 3)*SSTR;
        #pragma unroll
        for (int k16 = 0; k16 < 4; ++k16) {
            const int kh = 16*k16;
            uint32_t ay[4], al_[4];
            ldaW(ay,  st + O_YH, kh, lane, wm);
            ldaW(al_, st + O_YL, kh, lane, wm);
            if (PART & 1) {
                uint32_t b0[4];
                ldbW(b0, st + O_W0, kh, lane, wn);
                mma2(acc0, ay, b0); mma2(acc0, al_, b0);
            }
            if (PART & 2) {
                uint32_t b1w[4];
                ldbW(b1w, st + O_W1, kh, lane, wn);
                mma2(acc1, ay, b1w); mma2(acc1, al_, b1w);
                uint32_t ah[4], ahl[4], b2w[4];
                ldaW(ah,  st + O_HH, kh, lane, wm);
                ldaW(ahl, st + O_HL, kh, lane, wm);
                ldbW(b2w, st + O_W2, kh, lane, wn);
                mma2(acc1, ah, b2w); mma2(acc1, ahl, b2w);
            }
        }
    }

    if (PART & 1)
        epi(acc0, x + t*I_, S_*I_, eWih0, ebih0, ebhh0,
            g_ys0_hi + (size_t)t*BH, g_ys0_lo + (size_t)t*BH,
            bm0, bn0, lane, wm, wn);
    if (PART & 2)
        epi(acc1, nullptr, 0, nullptr, ebih1, ebhh1,
            g_h1hi + (size_t)((t-1)&1)*BH, g_h1lo + (size_t)((t-1)&1)*BH,
            bm0, bn0, lane, wm, wn);
}

// ---------------------------------------------------------------------------
// Decoder GEMM interval: C = tanh(A@WA (+ A2@WB) + [xs.Wsm] + b1 + b2)
// ---------------------------------------------------------------------------
template<int TWO>
__device__ void dec_step(
    const __half* __restrict__ Ah, const __half* __restrict__ Al,
    const __half* __restrict__ A2h, const __half* __restrict__ A2l,
    const __half* __restrict__ WA, const __half* __restrict__ WB,
    const float* __restrict__ xs, int xst, const float* __restrict__ Wsm,
    const float* __restrict__ b1, const float* __restrict__ b2,
    __half* __restrict__ Chi, __half* __restrict__ Clo,
    int bm0, int bn0, int tid, __half* sm)
{
    const int lane = tid & 31, wrp = tid >> 5, wm = wrp >> 2, wn = wrp & 3;
    const int lrow = tid >> 3, lcolh = (tid & 7) * 8;

    auto pf = [&](int c, int slot) {
        __half* st = sm + slot*SSTR;
        const int k0 = c*BK;
        const int r  = lrow;
        const int sc = lcolh ^ ((r & 7) * 8);
        uint32_t d;
        d = smaddr(st + O_YH + r*64 + sc); CP16(d, Ah + (size_t)(bm0 + r)*H_ + k0 + lcolh);
        d = smaddr(st + O_YL + r*64 + sc); CP16(d, Al + (size_t)(bm0 + r)*H_ + k0 + lcolh);
        if (TWO) {
            d = smaddr(st + O_HH + r*64 + sc); CP16(d, A2h + (size_t)(bm0 + r)*H_ + k0 + lcolh);
            d = smaddr(st + O_HL + r*64 + sc); CP16(d, A2l + (size_t)(bm0 + r)*H_ + k0 + lcolh);
        }
        #pragma unroll
        for (int i = 0; i < 2; ++i) {
            const int r2  = lrow + 32*i;
            const int sc2 = lcolh ^ ((r2 & 7) * 8);
            d = smaddr(st + O_W0 + r2*64 + sc2);
            CP16(d, WA + (size_t)(bn0 + r2)*H_ + k0 + lcolh);
            if (TWO) {
                d = smaddr(st + O_W1 + r2*64 + sc2);
                CP16(d, WB + (size_t)(bn0 + r2)*H_ + k0 + lcolh);
            }
        }
    };

    float acc[2][4] = {};
    pf(0, 0); asm volatile("cp.async.commit_group;");
    pf(1, 1); asm volatile("cp.async.commit_group;");

    for (int c = 0; c < KCH; ++c) {
        asm volatile("cp.async.wait_group 1;");
        __syncthreads();
        if (c + 2 < KCH) pf(c + 2, (c + 2) % 3);
        asm volatile("cp.async.commit_group;");

        const __half* st = sm + (c % 3)*SSTR;
        #pragma unroll
        for (int k16 = 0; k16 < 4; ++k16) {
            const int kh = 16*k16;
            uint32_t a1[4], a2[4], bA[4];
            ldaW(a1, st + O_YH, kh, lane, wm);
            ldaW(a2, st + O_YL, kh, lane, wm);
            ldbW(bA, st + O_W0, kh, lane, wn);
            mma2(acc, a1, bA); mma2(acc, a2, bA);
            if (TWO) {
                uint32_t a3[4], a4[4], bB[4];
                ldaW(a3, st + O_HH, kh, lane, wm);
                ldaW(a4, st + O_HL, kh, lane, wm);
                ldbW(bB, st + O_W1, kh, lane, wn);
                mma2(acc, a3, bB); mma2(acc, a4, bB);
            }
        }
    }
    epi(acc, xs, xst, Wsm, b1, b2, Chi, Clo, bm0, bn0, lane, wm, wn);
}

// ---------------------------------------------------------------------------
// Persistent whole-network kernel. 128 CTAs x 256 threads, 1 CTA/SM.
// ---------------------------------------------------------------------------
__global__ __launch_bounds__(256) void k_persist(
    const float* __restrict__ x,
    const float* __restrict__ eWih0, const float* __restrict__ ebih0, const float* __restrict__ ebhh0,
    const float* __restrict__ ebih1, const float* __restrict__ ebhh1,
    const float* __restrict__ dWih0, const float* __restrict__ dbih0, const float* __restrict__ dbhh0,
    const float* __restrict__ dbih1, const float* __restrict__ dbhh1,
    const float* __restrict__ dWlin, const float* __restrict__ dblin,
    float* __restrict__ out)
{
    extern __shared__ __half sm[];
    const int tid = threadIdx.x;
    const int bid = blockIdx.x;
    const int bn0 = (bid & 15) * BN;
    const int bm0 = (bid >> 4) * BM;

    // ---- Fused encoder: 258 intervals ----
    enc_step<1>(0, x, eWih0, ebih0, ebhh0, ebih1, ebhh1, bm0, bn0, tid, sm);
    gridbar(tid);
    for (int t = 1; t < S_; ++t) {
        enc_step<3>(t, x, eWih0, ebih0, ebhh0, ebih1, ebhh1, bm0, bn0, tid, sm);
        gridbar(tid);
    }
    enc_step<2>(S_, x, eWih0, ebih0, ebhh0, ebih1, ebhh1, bm0, bn0, tid, sm);
    gridbar(tid);

    // ---- Decoder ----
    const __half* pAh = g_ys0_hi + (size_t)(S_-1)*BH;
    const __half* pAl = g_ys0_lo + (size_t)(S_-1)*BH;
    const __half* pBh = g_h1hi + (size_t)((S_-1)&1)*BH;
    const __half* pBl = g_h1lo + (size_t)((S_-1)&1)*BH;
    for (int t = 0; t < T_; ++t) {
        __half* nAh = g_hAhi + (size_t)(t&1)*BH;
        __half* nAl = g_hAlo + (size_t)(t&1)*BH;
        dec_step<0>(pAh, pAl, nullptr, nullptr, g_W[3], nullptr,
                    g_inp, I_, dWih0, dbih0, dbhh0,
                    nAh, nAl, bm0, bn0, tid, sm);
        gridbar(tid);
        __half* nBh = g_hBhi + (size_t)(t&1)*BH;
        __half* nBl = g_hBlo + (size_t)(t&1)*BH;
        dec_step<1>(nAh, nAl, pBh, pBl, g_W[4], g_W[5],
                    nullptr, 0, nullptr, dbih1, dbhh1,
                    nBh, nBl, bm0, bn0, tid, sm);
        gridbar(tid);
        // decout + feedback: CTAs 0..31, one warp per batch row
        if (bid < 32) {
            const int row  = bid*8 + (tid >> 5);
            const int lane = tid & 31;
            const __half* hh = nBh + (size_t)row*H_;
            const __half* hl = nBl + (size_t)row*H_;
            float s = 0.0f;
            #pragma unroll 8
            for (int k = lane; k < H_; k += 32)
                s = fmaf(__half2float(hh[k]) + __half2float(hl[k]), dWlin[k], s);
            #pragma unroll
            for (int o = 16; o > 0; o >>= 1)
                s += __shfl_xor_sync(0xffffffffu, s, o);
            if (lane == 0) {
                const float o_ = s + dblin[0];
                out[row*T_ + t] = o_;
                const float i0 = g_inp[row*3 + 0];
                const float i1 = g_inp[row*3 + 1];
                const float c0 = o_;
                const float c1 = i0 - c0;
                const float c2 = i1 - c1;
                g_inp[row*3 + 0] = c0;
                g_inp[row*3 + 1] = c1;
                g_inp[row*3 + 2] = c2;
            }
        }
        gridbar(tid);
        pAh = nAh; pAl = nAl; pBh = nBh; pBl = nBl;
    }
}

// ---------------------------------------------------------------------------
// Orchestration: 3 launches on default stream (graph-capturable).
// ---------------------------------------------------------------------------
extern "C" void kernel_launch(void* const* d_in, const int* in_sizes, int n_in,
                              void* d_out, int out_size)
{
    (void)in_sizes; (void)n_in; (void)out_size;
    const float* x     = (const float*)d_in[0];
    const float* eWih0 = (const float*)d_in[2];
    const float* eWhh0 = (const float*)d_in[3];
    const float* ebih0 = (const float*)d_in[4];
    const float* ebhh0 = (const float*)d_in[5];
    const float* eWih1 = (const float*)d_in[6];
    const float* eWhh1 = (const float*)d_in[7];
    const float* ebih1 = (const float*)d_in[8];
    const float* ebhh1 = (const float*)d_in[9];
    const float* dWih0 = (const float*)d_in[10];
    const float* dWhh0 = (const float*)d_in[11];
    const float* dbih0 = (const float*)d_in[12];
    const float* dbhh0 = (const float*)d_in[13];
    const float* dWih1 = (const float*)d_in[14];
    const float* dWhh1 = (const float*)d_in[15];
    const float* dbih1 = (const float*)d_in[16];
    const float* dbhh1 = (const float*)d_in[17];
    const float* dWlin = (const float*)d_in[18];
    const float* dblin = (const float*)d_in[19];
    float* out = (float*)d_out;

    static bool s_attr = false;
    if (!s_attr) {
        cudaFuncSetAttribute(k_persist,
                             cudaFuncAttributeMaxDynamicSharedMemorySize, SMEM_BYTES);
        s_attr = true;
    }

    k_init<<<(BH + 255)/256, 256>>>(x);
    // order: eWhh0, eWih1, eWhh1, dWhh0, dWih1, dWhh1
    k_conv6<<<dim3(H_*H_/256, 6), 256>>>(eWhh0, eWih1, eWhh1, dWhh0, dWih1, dWhh1);
    k_persist<<<NCTA, THREADS, SMEM_BYTES>>>(x,
        eWih0, ebih0, ebhh0, ebih1, ebhh1,
        dWih0, dbih0, dbhh0, dbih1, dbhh1,
        dWlin, dblin, out);
}

// round 9
// speedup vs baseline: 1.6300x; 1.3704x over previous
#include <cuda_runtime.h>
#include <cuda_fp16.h>
#include <stdint.h>
#include <math.h>

// Problem dims (fixed)
#define B_ 256
#define S_ 256
#define I_ 3
#define H_ 1024
#define T_ 64
#define BH (B_*H_)

#define BM 32
#define BN 64
#define BK 64
#define KCH 16
#define NCTA 128
#define THREADS 256

// Shared memory layout (halves):
//  [0, WC_H)                : cached W slice, 16 chunks of 64x64 (128 KB)
//  [WC_H, WC_H+3*SSTR)      : 3 pipeline stages
#define WC_H (KCH*BN*BK)      // 65536 halves
#define O_A0 0                // A tile 0 (32x64)
#define O_A1 2048             // A tile 1 (32x64)
#define O_WA 4096             // streamed W tile A (64x64)
#define O_WB 8192             // streamed W tile B (64x64)
#define SSTR 12288
#define SMEM_BYTES ((WC_H + 3*SSTR)*2)   // 204800 B

// ---------------------------------------------------------------------------
// Device scratch (no allocation allowed)
// ---------------------------------------------------------------------------
__device__ __half g_y0[2*BH];            // enc layer-0 output ping-pong
__device__ __half g_h1[2*BH];            // enc layer-1 hidden ping-pong
__device__ __half g_hA[2*BH], g_hB[2*BH];
__device__ __half g_zb[BH];
__device__ float  g_inp[B_*I_];
// 0:eWhh0 1:eWih1 2:eWhh1 3:dWhh0 4:dWih1 5:dWhh1
__device__ __half g_W[6][H_*H_];
__device__ unsigned g_cnt;

// ---------------------------------------------------------------------------
__global__ void k_init(const float* __restrict__ x) {
    int i = blockIdx.x * blockDim.x + threadIdx.x;
    if (i == 0) g_cnt = 0;
    if (i < BH) g_zb[i] = __float2half(0.0f);
    if (i < B_*I_) {
        int b = i / I_, c = i % I_;
        g_inp[i] = x[b*(S_*I_) + (S_-1)*I_ + c];
    }
}

__global__ void k_conv6(const float* __restrict__ s0, const float* __restrict__ s1,
                        const float* __restrict__ s2, const float* __restrict__ s3,
                        const float* __restrict__ s4, const float* __restrict__ s5) {
    int i = blockIdx.x * blockDim.x + threadIdx.x;
    const float* srcs[6] = {s0, s1, s2, s3, s4, s5};
    int j = blockIdx.y;
    g_W[j][i] = __float2half(srcs[j][i]);
}

// ---------------------------------------------------------------------------
// Split grid barrier: monotonic counter, arrive early / wait late.
// ---------------------------------------------------------------------------
__device__ __forceinline__ void gb_arrive(int tid) {
    __syncthreads();
    if (tid == 0) { __threadfence(); atomicAdd(&g_cnt, 1u); }
}
__device__ __forceinline__ void gb_wait(int tid, unsigned target) {
    if (tid == 0) {
        while (*(volatile unsigned*)&g_cnt < target) { }
        __threadfence();
    }
    __syncthreads();
}

__device__ __forceinline__ uint32_t smaddr(const void* p) {
    return (uint32_t)__cvta_generic_to_shared(p);
}
#define CP16(dst_sm, src_gm) \
    asm volatile("cp.async.cg.shared.global [%0], [%1], 16;\n" \
                 :: "r"(dst_sm), "l"(src_gm))
#define CPCOMMIT() asm volatile("cp.async.commit_group;")
#define CPWAIT1()  asm volatile("cp.async.wait_group 1;")

// Load this CTA's 64x1024 W slice into the smem cache (16 swizzled chunks).
__device__ void loadWc(const __half* __restrict__ W, __half* Wc, int bn0, int tid) {
    const int lrow = tid >> 3, lcolh = (tid & 7) * 8;
    for (int kc = 0; kc < KCH; ++kc) {
        #pragma unroll
        for (int i = 0; i < 2; ++i) {
            int r  = lrow + 32*i;
            int sc = lcolh ^ ((r & 7) * 8);
            CP16(smaddr(Wc + kc*4096 + r*64 + sc),
                 W + (size_t)(bn0 + r)*H_ + kc*64 + lcolh);
        }
    }
    CPCOMMIT();
    asm volatile("cp.async.wait_group 0;");
    __syncthreads();
}

// Pre-barrier W-stream prefetch: chunks 0,1 into stages 0,1 (2 commit groups).
template<int NW>
__device__ void preW(const __half* __restrict__ WA, const __half* __restrict__ WB,
                     int bn0, int tid, __half* sm) {
    __half* stg = sm + WC_H;
    const int lrow = tid >> 3, lcolh = (tid & 7) * 8;
    for (int c = 0; c < 2; ++c) {
        __half* st = stg + c*SSTR;
        const int k0 = c*BK;
        #pragma unroll
        for (int i = 0; i < 2; ++i) {
            int r2  = lrow + 32*i;
            int sc2 = lcolh ^ ((r2 & 7) * 8);
            CP16(smaddr(st + O_WA + r2*64 + sc2), WA + (size_t)(bn0 + r2)*H_ + k0 + lcolh);
            if (NW == 2)
                CP16(smaddr(st + O_WB + r2*64 + sc2), WB + (size_t)(bn0 + r2)*H_ + k0 + lcolh);
        }
        CPCOMMIT();
    }
}

// ldmatrix helpers (row width 64 halves, XOR swizzle on 8-half granule)
__device__ __forceinline__ void ldaW(uint32_t a[4], const __half* base, int kh, int lane, int wm) {
    int r  = wm*16 + (lane & 15);
    int cc = (kh + ((lane >> 4) * 8)) ^ ((r & 7) * 8);
    uint32_t addr = smaddr(base + r*64 + cc);
    asm volatile("ldmatrix.sync.aligned.m8n8.x4.shared.b16 {%0,%1,%2,%3}, [%4];"
        : "=r"(a[0]), "=r"(a[1]), "=r"(a[2]), "=r"(a[3]) : "r"(addr));
}
__device__ __forceinline__ void ldbW(uint32_t b[4], const __half* base, int kh, int lane, int wn) {
    int j  = lane >> 3;
    int r  = wn*16 + ((j >> 1) * 8) + (lane & 7);
    int cc = (kh + (j & 1) * 8) ^ ((r & 7) * 8);
    uint32_t addr = smaddr(base + r*64 + cc);
    asm volatile("ldmatrix.sync.aligned.m8n8.x4.shared.b16 {%0,%1,%2,%3}, [%4];"
        : "=r"(b[0]), "=r"(b[1]), "=r"(b[2]), "=r"(b[3]) : "r"(addr));
}
__device__ __forceinline__ void mma2(float acc[2][4], const uint32_t a[4], const uint32_t b[4]) {
    #pragma unroll
    for (int ni = 0; ni < 2; ++ni)
        asm volatile(
            "mma.sync.aligned.m16n8k16.row.col.f32.f16.f16.f32 "
            "{%0,%1,%2,%3}, {%4,%5,%6,%7}, {%8,%9}, {%0,%1,%2,%3};"
            : "+f"(acc[ni][0]), "+f"(acc[ni][1]), "+f"(acc[ni][2]), "+f"(acc[ni][3])
            : "r"(a[0]), "r"(a[1]), "r"(a[2]), "r"(a[3]),
              "r"(b[2*ni]), "r"(b[2*ni+1]));
}

// Epilogue: optional rank-3 x-projection + biases, tanh, single fp16 write.
__device__ __forceinline__ void epi(
    float acc[2][4],
    const float* __restrict__ xs, int xs_stride, const float* __restrict__ Wsm,
    const float* __restrict__ b1, const float* __restrict__ b2,
    __half* __restrict__ C,
    int bm0, int bn0, int lane, int wm, int wn)
{
    #pragma unroll
    for (int h = 0; h < 2; ++h) {
        const int row = bm0 + wm*16 + (lane >> 2) + h*8;
        float x0 = 0.f, x1 = 0.f, x2 = 0.f;
        if (xs) {
            const float* xr = xs + (size_t)row * xs_stride;
            x0 = xr[0]; x1 = xr[1]; x2 = xr[2];
        }
        #pragma unroll
        for (int ni = 0; ni < 2; ++ni) {
            const int col = bn0 + wn*16 + ni*8 + (lane & 3)*2;
            float v0 = acc[ni][h*2 + 0];
            float v1 = acc[ni][h*2 + 1];
            if (xs) {
                v0 += x0*Wsm[col*3+0] + x1*Wsm[col*3+1] + x2*Wsm[col*3+2];
                v1 += x0*Wsm[(col+1)*3+0] + x1*Wsm[(col+1)*3+1] + x2*Wsm[(col+1)*3+2];
            }
            v0 += b1[col] + b2[col];
            v1 += b1[col+1] + b2[col+1];
            v0 = tanhf(v0); v1 = tanhf(v1);
            *(__half2*)(C + (size_t)row*H_ + col) =
                __halves2half2(__float2half(v0), __float2half(v1));
        }
    }
}

// ---------------------------------------------------------------------------
// Fused encoder interval t (entry: stages 0,1 hold W1/W2 chunks 0,1):
//   ENC0: ys0[t]  = tanh(x[t]@Wih0 + Y@W0cached + b)        (acc0)
//   always: h1[.] = tanh(Y@W1stream + H@W2stream + b)       (acc1)
// ---------------------------------------------------------------------------
template<int ENC0>
__device__ void enc_step(int t,
    const __half* __restrict__ Y, const __half* __restrict__ Hp,
    const float* __restrict__ x, const float* __restrict__ eWih0,
    const float* __restrict__ ebih0, const float* __restrict__ ebhh0,
    const float* __restrict__ ebih1, const float* __restrict__ ebhh1,
    __half* __restrict__ Yout, __half* __restrict__ Hout,
    int bm0, int bn0, int tid, __half* sm)
{
    const int lane = tid & 31, wrp = tid >> 5, wm = wrp >> 2, wn = wrp & 3;
    const int lrow = tid >> 3, lcolh = (tid & 7) * 8;
    __half* stg = sm + WC_H;

    auto pfA = [&](int c, int slot) {
        __half* st = stg + slot*SSTR;
        const int k0 = c*BK;
        const int r  = lrow;
        const int sc = lcolh ^ ((r & 7) * 8);
        CP16(smaddr(st + O_A0 + r*64 + sc), Y  + (size_t)(bm0 + r)*H_ + k0 + lcolh);
        CP16(smaddr(st + O_A1 + r*64 + sc), Hp + (size_t)(bm0 + r)*H_ + k0 + lcolh);
    };
    auto pfW = [&](int c, int slot) {
        __half* st = stg + slot*SSTR;
        const int k0 = c*BK;
        #pragma unroll
        for (int i = 0; i < 2; ++i) {
            int r2  = lrow + 32*i;
            int sc2 = lcolh ^ ((r2 & 7) * 8);
            CP16(smaddr(st + O_WA + r2*64 + sc2), g_W[1] + (size_t)(bn0 + r2)*H_ + k0 + lcolh);
            CP16(smaddr(st + O_WB + r2*64 + sc2), g_W[2] + (size_t)(bn0 + r2)*H_ + k0 + lcolh);
        }
    };

    pfA(0, 0); CPCOMMIT();
    pfA(1, 1); CPCOMMIT();

    float acc0[2][4] = {}, acc1[2][4] = {};
    for (int c = 0; c < KCH; ++c) {
        CPWAIT1();
        __syncthreads();
        if (c + 2 < KCH) { pfA(c + 2, (c + 2) % 3); pfW(c + 2, (c + 2) % 3); }
        CPCOMMIT();

        const __half* st = stg + (c % 3)*SSTR;
        #pragma unroll
        for (int k16 = 0; k16 < 4; ++k16) {
            const int kh = 16*k16;
            uint32_t ay[4];
            ldaW(ay, st + O_A0, kh, lane, wm);
            if (ENC0) {
                uint32_t bc[4];
                ldbW(bc, sm + c*4096, kh, lane, wn);
                mma2(acc0, ay, bc);
            }
            uint32_t b1w[4];
            ldbW(b1w, st + O_WA, kh, lane, wn);
            mma2(acc1, ay, b1w);
            uint32_t ah[4], b2w[4];
            ldaW(ah, st + O_A1, kh, lane, wm);
            ldbW(b2w, st + O_WB, kh, lane, wn);
            mma2(acc1, ah, b2w);
        }
    }

    if (ENC0)
        epi(acc0, x + t*I_, S_*I_, eWih0, ebih0, ebhh0, Yout, bm0, bn0, lane, wm, wn);
    epi(acc1, nullptr, 0, nullptr, ebih1, ebhh1, Hout, bm0, bn0, lane, wm, wn);
}

// ---------------------------------------------------------------------------
// Decoder interval (entry: stages 0,1 hold Wstr chunks 0,1):
//   TWO=0: C = tanh(A0@Wstr + xs.Wsm + b)          (dec layer 0, Wstr=dWhh0)
//   TWO=1: C = tanh(A0@Wstr + A1@W5cached + b)     (dec layer 1, Wstr=dWih1)
// ---------------------------------------------------------------------------
template<int TWO>
__device__ void dec_step(
    const __half* __restrict__ A0, const __half* __restrict__ A1,
    const __half* __restrict__ Wstr,
    const float* __restrict__ xs, int xst, const float* __restrict__ Wsm,
    const float* __restrict__ b1, const float* __restrict__ b2,
    __half* __restrict__ Cout,
    int bm0, int bn0, int tid, __half* sm)
{
    const int lane = tid & 31, wrp = tid >> 5, wm = wrp >> 2, wn = wrp & 3;
    const int lrow = tid >> 3, lcolh = (tid & 7) * 8;
    __half* stg = sm + WC_H;

    auto pfA = [&](int c, int slot) {
        __half* st = stg + slot*SSTR;
        const int k0 = c*BK;
        const int r  = lrow;
        const int sc = lcolh ^ ((r & 7) * 8);
        CP16(smaddr(st + O_A0 + r*64 + sc), A0 + (size_t)(bm0 + r)*H_ + k0 + lcolh);
        if (TWO)
            CP16(smaddr(st + O_A1 + r*64 + sc), A1 + (size_t)(bm0 + r)*H_ + k0 + lcolh);
    };
    auto pfW = [&](int c, int slot) {
        __half* st = stg + slot*SSTR;
        const int k0 = c*BK;
        #pragma unroll
        for (int i = 0; i < 2; ++i) {
            int r2  = lrow + 32*i;
            int sc2 = lcolh ^ ((r2 & 7) * 8);
            CP16(smaddr(st + O_WA + r2*64 + sc2), Wstr + (size_t)(bn0 + r2)*H_ + k0 + lcolh);
        }
    };

    pfA(0, 0); CPCOMMIT();
    pfA(1, 1); CPCOMMIT();

    float acc[2][4] = {};
    for (int c = 0; c < KCH; ++c) {
        CPWAIT1();
        __syncthreads();
        if (c + 2 < KCH) { pfA(c + 2, (c + 2) % 3); pfW(c + 2, (c + 2) % 3); }
        CPCOMMIT();

        const __half* st = stg + (c % 3)*SSTR;
        #pragma unroll
        for (int k16 = 0; k16 < 4; ++k16) {
            const int kh = 16*k16;
            uint32_t a0[4], bA[4];
            ldaW(a0, st + O_A0, kh, lane, wm);
            ldbW(bA, st + O_WA, kh, lane, wn);
            mma2(acc, a0, bA);
            if (TWO) {
                uint32_t a1[4], bc[4];
                ldaW(a1, st + O_A1, kh, lane, wm);
                ldbW(bc, sm + c*4096, kh, lane, wn);
                mma2(acc, a1, bc);
            }
        }
    }
    epi(acc, xs, xst, Wsm, b1, b2, Cout, bm0, bn0, lane, wm, wn);
}

// ---------------------------------------------------------------------------
// Persistent whole-network kernel. 128 CTAs x 256 threads, 1 CTA/SM.
// ---------------------------------------------------------------------------
__global__ __launch_bounds__(256) void k_persist(
    const float* __restrict__ x,
    const float* __restrict__ eWih0, const float* __restrict__ ebih0, const float* __restrict__ ebhh0,
    const float* __restrict__ ebih1, const float* __restrict__ ebhh1,
    const float* __restrict__ dWih0, const float* __restrict__ dbih0, const float* __restrict__ dbhh0,
    const float* __restrict__ dbih1, const float* __restrict__ dbhh1,
    const float* __restrict__ dWlin, const float* __restrict__ dblin,
    float* __restrict__ out)
{
    extern __shared__ __half sm[];
    const int tid = threadIdx.x;
    const int bid = blockIdx.x;
    const int bn0 = (bid & 15) * BN;
    const int bm0 = (bid >> 4) * BM;
    const int lane = tid & 31, wrp = tid >> 5, wm = wrp >> 2, wn = wrp & 3;
    unsigned nb = 0;

    // Cache W0 (eWhh0) slice for the encoder phase.
    loadWc(g_W[0], sm, bn0, tid);

    // t=0: ys0[0] = tanh(x[0]@Wih0 + b) — epilogue only (Y = 0).
    {
        float z[2][4] = {};
        epi(z, x, S_*I_, eWih0, ebih0, ebhh0, g_y0, bm0, bn0, lane, wm, wn);
    }
    gb_arrive(tid);
    preW<2>(g_W[1], g_W[2], bn0, tid, sm);
    gb_wait(tid, NCTA * (++nb));

    // ---- Fused encoder: t = 1..255 (enc0[t] + enc1[t-1]) ----
    for (int t = 1; t < S_; ++t) {
        const __half* Y  = g_y0 + (size_t)((t-1)&1)*BH;
        const __half* Hp = (t >= 2) ? g_h1 + (size_t)((t-2)&1)*BH : g_zb;
        enc_step<1>(t, Y, Hp, x, eWih0, ebih0, ebhh0, ebih1, ebhh1,
                    g_y0 + (size_t)(t&1)*BH, g_h1 + (size_t)((t-1)&1)*BH,
                    bm0, bn0, tid, sm);
        gb_arrive(tid);
        preW<2>(g_W[1], g_W[2], bn0, tid, sm);
        gb_wait(tid, NCTA * (++nb));
    }
    // t = 256: enc1[255] only.
    enc_step<0>(S_, g_y0 + (size_t)((S_-1)&1)*BH, g_h1 + (size_t)((S_-2)&1)*BH,
                x, eWih0, ebih0, ebhh0, ebih1, ebhh1,
                g_y0, g_h1 + (size_t)((S_-1)&1)*BH, bm0, bn0, tid, sm);

    // Swap W cache to W5 (dWhh1) during the barrier window; prefetch W3.
    gb_arrive(tid);
    loadWc(g_W[5], sm, bn0, tid);
    preW<1>(g_W[3], nullptr, bn0, tid, sm);
    gb_wait(tid, NCTA * (++nb));

    // ---- Decoder ----
    const __half* pA = g_y0 + (size_t)((S_-1)&1)*BH;   // h_enc0
    const __half* pB = g_h1 + (size_t)((S_-1)&1)*BH;   // h_enc1
    for (int t = 0; t < T_; ++t) {
        __half* nA = g_hA + (size_t)(t&1)*BH;
        dec_step<0>(pA, nullptr, g_W[3], g_inp, I_, dWih0, dbih0, dbhh0,
                    nA, bm0, bn0, tid, sm);
        gb_arrive(tid);
        preW<1>(g_W[4], nullptr, bn0, tid, sm);
        gb_wait(tid, NCTA * (++nb));

        __half* nB = g_hB + (size_t)(t&1)*BH;
        dec_step<1>(nA, pB, g_W[4], nullptr, 0, nullptr, dbih1, dbhh1,
                    nB, bm0, bn0, tid, sm);
        gb_arrive(tid);
        if (t + 1 < T_) preW<1>(g_W[3], nullptr, bn0, tid, sm);
        gb_wait(tid, NCTA * (++nb));

        // decout + feedback: CTAs 0..31, one warp per batch row.
        if (bid < 32) {
            const int row = bid*8 + wrp;
            const __half* hh = nB + (size_t)row*H_;
            float s = 0.0f;
            #pragma unroll 8
            for (int k = lane; k < H_; k += 32)
                s = fmaf(__half2float(hh[k]), dWlin[k], s);
            #pragma unroll
            for (int o = 16; o > 0; o >>= 1)
                s += __shfl_xor_sync(0xffffffffu, s, o);
            if (lane == 0) {
                const float o_ = s + dblin[0];
                out[row*T_ + t] = o_;
                const float i0 = g_inp[row*3 + 0];
                const float i1 = g_inp[row*3 + 1];
                const float c0 = o_;
                const float c1 = i0 - c0;
                const float c2 = i1 - c1;
                g_inp[row*3 + 0] = c0;
                g_inp[row*3 + 1] = c1;
                g_inp[row*3 + 2] = c2;
            }
        }
        if (t + 1 < T_) {
            gb_arrive(tid);
            gb_wait(tid, NCTA * (++nb));
        }
        pA = nA; pB = nB;
    }
}

// ---------------------------------------------------------------------------
// Orchestration: 3 launches on default stream (graph-capturable).
// ---------------------------------------------------------------------------
extern "C" void kernel_launch(void* const* d_in, const int* in_sizes, int n_in,
                              void* d_out, int out_size)
{
    (void)in_sizes; (void)n_in; (void)out_size;
    const float* x     = (const float*)d_in[0];
    const float* eWih0 = (const float*)d_in[2];
    const float* eWhh0 = (const float*)d_in[3];
    const float* ebih0 = (const float*)d_in[4];
    const float* ebhh0 = (const float*)d_in[5];
    const float* eWih1 = (const float*)d_in[6];
    const float* eWhh1 = (const float*)d_in[7];
    const float* ebih1 = (const float*)d_in[8];
    const float* ebhh1 = (const float*)d_in[9];
    const float* dWih0 = (const float*)d_in[10];
    const float* dWhh0 = (const float*)d_in[11];
    const float* dbih0 = (const float*)d_in[12];
    const float* dbhh0 = (const float*)d_in[13];
    const float* dWih1 = (const float*)d_in[14];
    const float* dWhh1 = (const float*)d_in[15];
    const float* dbih1 = (const float*)d_in[16];
    const float* dbhh1 = (const float*)d_in[17];
    const float* dWlin = (const float*)d_in[18];
    const float* dblin = (const float*)d_in[19];
    float* out = (float*)d_out;

    static bool s_attr = false;
    if (!s_attr) {
        cudaFuncSetAttribute(k_persist,
                             cudaFuncAttributeMaxDynamicSharedMemorySize, SMEM_BYTES);
        s_attr = true;
    }

    k_init<<<(BH + 255)/256, 256>>>(x);
    // order: eWhh0, eWih1, eWhh1, dWhh0, dWih1, dWhh1
    k_conv6<<<dim3(H_*H_/256, 6), 256>>>(eWhh0, eWih1, eWhh1, dWhh0, dWih1, dWhh1);
    k_persist<<<NCTA, THREADS, SMEM_BYTES>>>(x,
        eWih0, ebih0, ebhh0, ebih1, ebhh1,
        dWih0, dbih0, dbhh0, dbih1, dbhh1,
        dWlin, dblin, out);
}

// round 10
// speedup vs baseline: 1.8392x; 1.1284x over previous
#include <cuda_runtime.h>
#include <cuda_fp16.h>
#include <stdint.h>
#include <math.h>

// Problem dims (fixed)
#define B_ 256
#define S_ 256
#define I_ 3
#define H_ 1024
#define T_ 64
#define BH (B_*H_)

#define BM 32
#define BN 64
#define BK 64
#define KCH 16
#define NCTA 128
#define THREADS 256
#define NSTG 4
#define GSZ 16            // CTAs per barrier group (one bm row-band)

// Shared memory layout (halves):
//  [0, WC_H)             : cached W slice, 16 chunks of 64x64 (128 KB)
//  [WC_H, WC_H+4*SSTR)   : 4 pipeline stages (A0,A1,WA,WB per stage)
#define WC_H (KCH*BN*BK)  // 65536 halves
#define O_A0 0
#define O_A1 2048
#define O_WA 4096
#define O_WB 8192
#define SSTR 12288
#define SMEM_BYTES ((WC_H + NSTG*SSTR)*2)   // 229376 B

// ---------------------------------------------------------------------------
// Device scratch (no allocation allowed)
// ---------------------------------------------------------------------------
__device__ __half g_y0[2*BH];
__device__ __half g_h1[2*BH];
__device__ __half g_hA[2*BH], g_hB[2*BH];
__device__ __half g_zb[BH];
__device__ float  g_inp[2*B_*I_];        // feedback ping-pong
// 0:eWhh0 1:eWih1 2:eWhh1 3:dWhh0 4:dWih1 5:dWhh1
__device__ __half g_W[6][H_*H_];
__device__ unsigned g_cnt[8*32];         // per-group counters, padded

// ---------------------------------------------------------------------------
__global__ void k_init(const float* __restrict__ x) {
    int i = blockIdx.x * blockDim.x + threadIdx.x;
    if (i < 8) g_cnt[i*32] = 0;
    if (i < BH) g_zb[i] = __float2half(0.0f);
    if (i < B_*I_) {
        int b = i / I_, c = i % I_;
        g_inp[B_*I_ + i] = x[b*(S_*I_) + (S_-1)*I_ + c];   // slot 1 = initial
    }
}

__global__ void k_conv6(const float* __restrict__ s0, const float* __restrict__ s1,
                        const float* __restrict__ s2, const float* __restrict__ s3,
                        const float* __restrict__ s4, const float* __restrict__ s5) {
    int i = blockIdx.x * blockDim.x + threadIdx.x;
    const float* srcs[6] = {s0, s1, s2, s3, s4, s5};
    int j = blockIdx.y;
    g_W[j][i] = __float2half(srcs[j][i]);
}

// ---------------------------------------------------------------------------
// Per-group (16-CTA) split barrier: monotonic counter, arrive early/wait late.
// Groups (row bands) are fully independent — no cross-group state.
// ---------------------------------------------------------------------------
__device__ __forceinline__ void gb_arrive(int tid, int grp) {
    __syncthreads();
    if (tid == 0) { __threadfence(); atomicAdd(&g_cnt[grp*32], 1u); }
}
__device__ __forceinline__ void gb_wait(int tid, int grp, unsigned target) {
    if (tid == 0) {
        while (*(volatile unsigned*)&g_cnt[grp*32] < target) { }
        __threadfence();
    }
    __syncthreads();
}

__device__ __forceinline__ uint32_t smaddr(const void* p) {
    return (uint32_t)__cvta_generic_to_shared(p);
}
#define CP16(dst_sm, src_gm) \
    asm volatile("cp.async.cg.shared.global [%0], [%1], 16;\n" \
                 :: "r"(dst_sm), "l"(src_gm))
#define CPCOMMIT() asm volatile("cp.async.commit_group;")
#define CPWAIT2()  asm volatile("cp.async.wait_group 2;")

// Load this CTA's 64x1024 W slice into the smem cache (16 swizzled chunks).
__device__ void loadWc(const __half* __restrict__ W, __half* Wc, int bn0, int tid) {
    const int lrow = tid >> 3, lcolh = (tid & 7) * 8;
    for (int kc = 0; kc < KCH; ++kc) {
        #pragma unroll
        for (int i = 0; i < 2; ++i) {
            int r  = lrow + 32*i;
            int sc = lcolh ^ ((r & 7) * 8);
            CP16(smaddr(Wc + kc*4096 + r*64 + sc),
                 W + (size_t)(bn0 + r)*H_ + kc*64 + lcolh);
        }
    }
    CPCOMMIT();
    asm volatile("cp.async.wait_group 0;");
    __syncthreads();
}

// Pre-barrier W-stream prefetch: chunks 0..2 into stages 0..2 (3 groups).
template<int NW>
__device__ void preW3(const __half* __restrict__ WA, const __half* __restrict__ WB,
                      int bn0, int tid, __half* sm) {
    __half* stg = sm + WC_H;
    const int lrow = tid >> 3, lcolh = (tid & 7) * 8;
    #pragma unroll
    for (int c = 0; c < 3; ++c) {
        __half* st = stg + c*SSTR;
        const int k0 = c*BK;
        #pragma unroll
        for (int i = 0; i < 2; ++i) {
            int r2  = lrow + 32*i;
            int sc2 = lcolh ^ ((r2 & 7) * 8);
            CP16(smaddr(st + O_WA + r2*64 + sc2), WA + (size_t)(bn0 + r2)*H_ + k0 + lcolh);
            if (NW == 2)
                CP16(smaddr(st + O_WB + r2*64 + sc2), WB + (size_t)(bn0 + r2)*H_ + k0 + lcolh);
        }
        CPCOMMIT();
    }
}

// ldmatrix helpers (row width 64 halves, XOR swizzle on 8-half granule)
__device__ __forceinline__ void ldaW(uint32_t a[4], const __half* base, int kh, int lane, int wm) {
    int r  = wm*16 + (lane & 15);
    int cc = (kh + ((lane >> 4) * 8)) ^ ((r & 7) * 8);
    uint32_t addr = smaddr(base + r*64 + cc);
    asm volatile("ldmatrix.sync.aligned.m8n8.x4.shared.b16 {%0,%1,%2,%3}, [%4];"
        : "=r"(a[0]), "=r"(a[1]), "=r"(a[2]), "=r"(a[3]) : "r"(addr));
}
__device__ __forceinline__ void ldbW(uint32_t b[4], const __half* base, int kh, int lane, int wn) {
    int j  = lane >> 3;
    int r  = wn*16 + ((j >> 1) * 8) + (lane & 7);
    int cc = (kh + (j & 1) * 8) ^ ((r & 7) * 8);
    uint32_t addr = smaddr(base + r*64 + cc);
    asm volatile("ldmatrix.sync.aligned.m8n8.x4.shared.b16 {%0,%1,%2,%3}, [%4];"
        : "=r"(b[0]), "=r"(b[1]), "=r"(b[2]), "=r"(b[3]) : "r"(addr));
}
__device__ __forceinline__ void mma2(float acc[2][4], const uint32_t a[4], const uint32_t b[4]) {
    #pragma unroll
    for (int ni = 0; ni < 2; ++ni)
        asm volatile(
            "mma.sync.aligned.m16n8k16.row.col.f32.f16.f16.f32 "
            "{%0,%1,%2,%3}, {%4,%5,%6,%7}, {%8,%9}, {%0,%1,%2,%3};"
            : "+f"(acc[ni][0]), "+f"(acc[ni][1]), "+f"(acc[ni][2]), "+f"(acc[ni][3])
            : "r"(a[0]), "r"(a[1]), "r"(a[2]), "r"(a[3]),
              "r"(b[2*ni]), "r"(b[2*ni+1]));
}

// Generic epilogue: optional x-projection + biases, tanh, fp16 write.
__device__ __forceinline__ void epi(
    float acc[2][4],
    const float* __restrict__ xs, int xs_stride, const float* __restrict__ Wsm,
    const float* __restrict__ b1, const float* __restrict__ b2,
    __half* __restrict__ C,
    int bm0, int bn0, int lane, int wm, int wn)
{
    #pragma unroll
    for (int h = 0; h < 2; ++h) {
        const int row = bm0 + wm*16 + (lane >> 2) + h*8;
        float x0 = 0.f, x1 = 0.f, x2 = 0.f;
        if (xs) {
            const float* xr = xs + (size_t)row * xs_stride;
            x0 = xr[0]; x1 = xr[1]; x2 = xr[2];
        }
        #pragma unroll
        for (int ni = 0; ni < 2; ++ni) {
            const int col = bn0 + wn*16 + ni*8 + (lane & 3)*2;
            float v0 = acc[ni][h*2 + 0];
            float v1 = acc[ni][h*2 + 1];
            if (xs) {
                v0 += x0*Wsm[col*3+0] + x1*Wsm[col*3+1] + x2*Wsm[col*3+2];
                v1 += x0*Wsm[(col+1)*3+0] + x1*Wsm[(col+1)*3+1] + x2*Wsm[(col+1)*3+2];
            }
            v0 += b1[col] + b2[col];
            v1 += b1[col+1] + b2[col+1];
            v0 = tanhf(v0); v1 = tanhf(v1);
            *(__half2*)(C + (size_t)row*H_ + col) =
                __halves2half2(__float2half(v0), __float2half(v1));
        }
    }
}

// ---------------------------------------------------------------------------
// Fused encoder interval t (entry: W chunks 0..2 pre-issued into stages 0..2):
//   ENC0: ys0[t]  = tanh(x[t]@Wih0 + Y@W0cached + b)        (acc0)
//   always: h1[.] = tanh(Y@W1stream + H@W2stream + b)       (acc1)
// ---------------------------------------------------------------------------
template<int ENC0>
__device__ void enc_step(int t,
    const __half* __restrict__ Y, const __half* __restrict__ Hp,
    const float* __restrict__ x, const float* __restrict__ eWih0,
    const float* __restrict__ ebih0, const float* __restrict__ ebhh0,
    const float* __restrict__ ebih1, const float* __restrict__ ebhh1,
    __half* __restrict__ Yout, __half* __restrict__ Hout,
    int bm0, int bn0, int tid, __half* sm)
{
    const int lane = tid & 31, wrp = tid >> 5, wm = wrp >> 2, wn = wrp & 3;
    const int lrow = tid >> 3, lcolh = (tid & 7) * 8;
    __half* stg = sm + WC_H;

    auto pfA = [&](int c, int slot) {
        __half* st = stg + slot*SSTR;
        const int k0 = c*BK;
        const int r  = lrow;
        const int sc = lcolh ^ ((r & 7) * 8);
        CP16(smaddr(st + O_A0 + r*64 + sc), Y  + (size_t)(bm0 + r)*H_ + k0 + lcolh);
        CP16(smaddr(st + O_A1 + r*64 + sc), Hp + (size_t)(bm0 + r)*H_ + k0 + lcolh);
    };
    auto pfW = [&](int c, int slot) {
        __half* st = stg + slot*SSTR;
        const int k0 = c*BK;
        #pragma unroll
        for (int i = 0; i < 2; ++i) {
            int r2  = lrow + 32*i;
            int sc2 = lcolh ^ ((r2 & 7) * 8);
            CP16(smaddr(st + O_WA + r2*64 + sc2), g_W[1] + (size_t)(bn0 + r2)*H_ + k0 + lcolh);
            CP16(smaddr(st + O_WB + r2*64 + sc2), g_W[2] + (size_t)(bn0 + r2)*H_ + k0 + lcolh);
        }
    };

    pfA(0, 0); CPCOMMIT();
    pfA(1, 1); CPCOMMIT();
    pfA(2, 2); CPCOMMIT();

    float acc0[2][4] = {}, acc1[2][4] = {};
    for (int c = 0; c < KCH; ++c) {
        CPWAIT2();
        __syncthreads();
        if (c + 3 < KCH) { pfW(c + 3, (c + 3) & 3); pfA(c + 3, (c + 3) & 3); }
        CPCOMMIT();

        const __half* st = stg + (c & 3)*SSTR;
        #pragma unroll
        for (int k16 = 0; k16 < 4; ++k16) {
            const int kh = 16*k16;
            uint32_t ay[4];
            ldaW(ay, st + O_A0, kh, lane, wm);
            if (ENC0) {
                uint32_t bc[4];
                ldbW(bc, sm + c*4096, kh, lane, wn);
                mma2(acc0, ay, bc);
            }
            uint32_t b1w[4];
            ldbW(b1w, st + O_WA, kh, lane, wn);
            mma2(acc1, ay, b1w);
            uint32_t ah[4], b2w[4];
            ldaW(ah, st + O_A1, kh, lane, wm);
            ldbW(b2w, st + O_WB, kh, lane, wn);
            mma2(acc1, ah, b2w);
        }
    }

    if (ENC0)
        epi(acc0, x + t*I_, S_*I_, eWih0, ebih0, ebhh0, Yout, bm0, bn0, lane, wm, wn);
    epi(acc1, nullptr, 0, nullptr, ebih1, ebhh1, Hout, bm0, bn0, lane, wm, wn);
}

// ---------------------------------------------------------------------------
// Decoder layer-0 interval (W3=dWhh0 streamed; entry: W chunks 0..2 staged):
//   hA = tanh(A0@W3 + inp@dWih0 + b); inp computed on the fly from out[:,t-1].
// ---------------------------------------------------------------------------
template<int FB>
__device__ void dec0(
    const __half* __restrict__ A0,
    const float* __restrict__ dWih0,
    const float* __restrict__ b1, const float* __restrict__ b2,
    const float* __restrict__ inp_prev, float* __restrict__ inp_cur,
    float* __restrict__ out, int t, const float* __restrict__ dblin,
    __half* __restrict__ Cout,
    int bm0, int bn0, int tid, __half* sm)
{
    const int lane = tid & 31, wrp = tid >> 5, wm = wrp >> 2, wn = wrp & 3;
    const int lrow = tid >> 3, lcolh = (tid & 7) * 8;
    __half* stg = sm + WC_H;

    auto pfA = [&](int c, int slot) {
        __half* st = stg + slot*SSTR;
        const int k0 = c*BK;
        const int r  = lrow;
        const int sc = lcolh ^ ((r & 7) * 8);
        CP16(smaddr(st + O_A0 + r*64 + sc), A0 + (size_t)(bm0 + r)*H_ + k0 + lcolh);
    };
    auto pfW = [&](int c, int slot) {
        __half* st = stg + slot*SSTR;
        const int k0 = c*BK;
        #pragma unroll
        for (int i = 0; i < 2; ++i) {
            int r2  = lrow + 32*i;
            int sc2 = lcolh ^ ((r2 & 7) * 8);
            CP16(smaddr(st + O_WA + r2*64 + sc2), g_W[3] + (size_t)(bn0 + r2)*H_ + k0 + lcolh);
        }
    };

    pfA(0, 0); CPCOMMIT();
    pfA(1, 1); CPCOMMIT();
    pfA(2, 2); CPCOMMIT();

    float acc[2][4] = {};
    for (int c = 0; c < KCH; ++c) {
        CPWAIT2();
        __syncthreads();
        if (c + 3 < KCH) { pfW(c + 3, (c + 3) & 3); pfA(c + 3, (c + 3) & 3); }
        CPCOMMIT();

        const __half* st = stg + (c & 3)*SSTR;
        #pragma unroll
        for (int k16 = 0; k16 < 4; ++k16) {
            const int kh = 16*k16;
            uint32_t a0[4], bA[4];
            ldaW(a0, st + O_A0, kh, lane, wm);
            ldbW(bA, st + O_WA, kh, lane, wn);
            mma2(acc, a0, bA);
        }
    }

    // Epilogue with on-the-fly feedback.
    #pragma unroll
    for (int h = 0; h < 2; ++h) {
        const int row = bm0 + wm*16 + (lane >> 2) + h*8;
        float c0, c1, c2;
        if (FB) {
            c0 = out[row*T_ + (t-1)];
            const float i0 = inp_prev[row*3 + 0];
            const float i1 = inp_prev[row*3 + 1];
            c1 = i0 - c0;
            c2 = i1 - c1;
        } else {
            c0 = inp_prev[row*3 + 0];
            c1 = inp_prev[row*3 + 1];
            c2 = inp_prev[row*3 + 2];
        }
        #pragma unroll
        for (int ni = 0; ni < 2; ++ni) {
            const int col = bn0 + wn*16 + ni*8 + (lane & 3)*2;
            float v0 = acc[ni][h*2 + 0];
            float v1 = acc[ni][h*2 + 1];
            v0 += c0*dWih0[col*3+0] + c1*dWih0[col*3+1] + c2*dWih0[col*3+2];
            v1 += c0*dWih0[(col+1)*3+0] + c1*dWih0[(col+1)*3+1] + c2*dWih0[(col+1)*3+2];
            v0 += b1[col] + b2[col];
            v1 += b1[col+1] + b2[col+1];
            v0 = tanhf(v0); v1 = tanhf(v1);
            *(__half2*)(Cout + (size_t)row*H_ + col) =
                __halves2half2(__float2half(v0), __float2half(v1));
        }
        if (bn0 == 0 && wn == 0 && (lane & 3) == 0) {
            inp_cur[row*3 + 0] = c0;
            inp_cur[row*3 + 1] = c1;
            inp_cur[row*3 + 2] = c2;
            out[row*T_ + t] = dblin[0];   // init for dec1's atomic partial dots
        }
    }
}

// ---------------------------------------------------------------------------
// Decoder layer-1 interval (W4=dWih1 streamed, W5=dWhh1 cached):
//   hB = tanh(A0@W4 + A1@W5c + b); fused decout: atomicAdd partial hB.Wlin.
// ---------------------------------------------------------------------------
__device__ void dec1(
    const __half* __restrict__ A0, const __half* __restrict__ A1,
    const float* __restrict__ b1, const float* __restrict__ b2,
    const float* __restrict__ Wlin,
    float* __restrict__ out, int t,
    __half* __restrict__ Cout,
    int bm0, int bn0, int tid, __half* sm)
{
    const int lane = tid & 31, wrp = tid >> 5, wm = wrp >> 2, wn = wrp & 3;
    const int lrow = tid >> 3, lcolh = (tid & 7) * 8;
    __half* stg = sm + WC_H;

    auto pfA = [&](int c, int slot) {
        __half* st = stg + slot*SSTR;
        const int k0 = c*BK;
        const int r  = lrow;
        const int sc = lcolh ^ ((r & 7) * 8);
        CP16(smaddr(st + O_A0 + r*64 + sc), A0 + (size_t)(bm0 + r)*H_ + k0 + lcolh);
        CP16(smaddr(st + O_A1 + r*64 + sc), A1 + (size_t)(bm0 + r)*H_ + k0 + lcolh);
    };
    auto pfW = [&](int c, int slot) {
        __half* st = stg + slot*SSTR;
        const int k0 = c*BK;
        #pragma unroll
        for (int i = 0; i < 2; ++i) {
            int r2  = lrow + 32*i;
            int sc2 = lcolh ^ ((r2 & 7) * 8);
            CP16(smaddr(st + O_WA + r2*64 + sc2), g_W[4] + (size_t)(bn0 + r2)*H_ + k0 + lcolh);
        }
    };

    pfA(0, 0); CPCOMMIT();
    pfA(1, 1); CPCOMMIT();
    pfA(2, 2); CPCOMMIT();

    float acc[2][4] = {};
    for (int c = 0; c < KCH; ++c) {
        CPWAIT2();
        __syncthreads();
        if (c + 3 < KCH) { pfW(c + 3, (c + 3) & 3); pfA(c + 3, (c + 3) & 3); }
        CPCOMMIT();

        const __half* st = stg + (c & 3)*SSTR;
        #pragma unroll
        for (int k16 = 0; k16 < 4; ++k16) {
            const int kh = 16*k16;
            uint32_t a0[4], bA[4];
            ldaW(a0, st + O_A0, kh, lane, wm);
            ldbW(bA, st + O_WA, kh, lane, wn);
            mma2(acc, a0, bA);
            uint32_t a1[4], bc[4];
            ldaW(a1, st + O_A1, kh, lane, wm);
            ldbW(bc, sm + c*4096, kh, lane, wn);
            mma2(acc, a1, bc);
        }
    }

    // Epilogue + fused decout partial dot.
    #pragma unroll
    for (int h = 0; h < 2; ++h) {
        const int row = bm0 + wm*16 + (lane >> 2) + h*8;
        float s = 0.0f;
        #pragma unroll
        for (int ni = 0; ni < 2; ++ni) {
            const int col = bn0 + wn*16 + ni*8 + (lane & 3)*2;
            float v0 = acc[ni][h*2 + 0] + b1[col] + b2[col];
            float v1 = acc[ni][h*2 + 1] + b1[col+1] + b2[col+1];
            v0 = tanhf(v0); v1 = tanhf(v1);
            *(__half2*)(Cout + (size_t)row*H_ + col) =
                __halves2half2(__float2half(v0), __float2half(v1));
            s += v0*Wlin[col] + v1*Wlin[col+1];
        }
        s += __shfl_xor_sync(0xffffffffu, s, 1);
        s += __shfl_xor_sync(0xffffffffu, s, 2);
        if ((lane & 3) == 0)
            atomicAdd(&out[row*T_ + t], s);
    }
}

// ---------------------------------------------------------------------------
// Persistent whole-network kernel. 128 CTAs x 256 threads, 1 CTA/SM.
// ---------------------------------------------------------------------------
__global__ __launch_bounds__(256) void k_persist(
    const float* __restrict__ x,
    const float* __restrict__ eWih0, const float* __restrict__ ebih0, const float* __restrict__ ebhh0,
    const float* __restrict__ ebih1, const float* __restrict__ ebhh1,
    const float* __restrict__ dWih0, const float* __restrict__ dbih0, const float* __restrict__ dbhh0,
    const float* __restrict__ dbih1, const float* __restrict__ dbhh1,
    const float* __restrict__ dWlin, const float* __restrict__ dblin,
    float* __restrict__ out)
{
    extern __shared__ __half sm[];
    const int tid = threadIdx.x;
    const int bid = blockIdx.x;
    const int bn0 = (bid & 15) * BN;
    const int bm0 = (bid >> 4) * BM;
    const int grp = bid >> 4;
    const int lane = tid & 31, wrp = tid >> 5, wm = wrp >> 2, wn = wrp & 3;
    unsigned nb = 0;

    // Cache W0 (eWhh0) slice for the encoder phase.
    loadWc(g_W[0], sm, bn0, tid);

    // t=0: ys0[0] = tanh(x[0]@Wih0 + b) — epilogue only (Y = 0).
    {
        float z[2][4] = {};
        epi(z, x, S_*I_, eWih0, ebih0, ebhh0, g_y0, bm0, bn0, lane, wm, wn);
    }
    gb_arrive(tid, grp);
    preW3<2>(g_W[1], g_W[2], bn0, tid, sm);
    gb_wait(tid, grp, GSZ * (++nb));

    // ---- Fused encoder: t = 1..255 (enc0[t] + enc1[t-1]) ----
    for (int t = 1; t < S_; ++t) {
        const __half* Y  = g_y0 + (size_t)((t-1)&1)*BH;
        const __half* Hp = (t >= 2) ? g_h1 + (size_t)((t-2)&1)*BH : g_zb;
        enc_step<1>(t, Y, Hp, x, eWih0, ebih0, ebhh0, ebih1, ebhh1,
                    g_y0 + (size_t)(t&1)*BH, g_h1 + (size_t)((t-1)&1)*BH,
                    bm0, bn0, tid, sm);
        gb_arrive(tid, grp);
        preW3<2>(g_W[1], g_W[2], bn0, tid, sm);
        gb_wait(tid, grp, GSZ * (++nb));
    }
    // t = 256: enc1[255] only.
    enc_step<0>(S_, g_y0 + (size_t)((S_-1)&1)*BH, g_h1 + (size_t)((S_-2)&1)*BH,
                x, eWih0, ebih0, ebhh0, ebih1, ebhh1,
                g_y0, g_h1 + (size_t)((S_-1)&1)*BH, bm0, bn0, tid, sm);

    // Swap W cache to W5 (dWhh1); prefetch W3 stream for dec0.
    gb_arrive(tid, grp);
    loadWc(g_W[5], sm, bn0, tid);
    preW3<1>(g_W[3], nullptr, bn0, tid, sm);
    gb_wait(tid, grp, GSZ * (++nb));

    // ---- Decoder: 2 barrier intervals per step ----
    const __half* pA = g_y0 + (size_t)((S_-1)&1)*BH;   // h_enc0
    const __half* pB = g_h1 + (size_t)((S_-1)&1)*BH;   // h_enc1
    for (int t = 0; t < T_; ++t) {
        __half* nA = g_hA + (size_t)(t&1)*BH;
        const float* inp_prev = g_inp + (size_t)((t-1)&1)*B_*I_;
        float* inp_cur = g_inp + (size_t)(t&1)*B_*I_;
        if (t == 0)
            dec0<0>(pA, dWih0, dbih0, dbhh0, inp_prev, inp_cur,
                    out, t, dblin, nA, bm0, bn0, tid, sm);
        else
            dec0<1>(pA, dWih0, dbih0, dbhh0, inp_prev, inp_cur,
                    out, t, dblin, nA, bm0, bn0, tid, sm);
        gb_arrive(tid, grp);
        preW3<1>(g_W[4], nullptr, bn0, tid, sm);
        gb_wait(tid, grp, GSZ * (++nb));

        __half* nB = g_hB + (size_t)(t&1)*BH;
        dec1(nA, pB, dbih1, dbhh1, dWlin, out, t, nB, bm0, bn0, tid, sm);
        gb_arrive(tid, grp);
        if (t + 1 < T_) preW3<1>(g_W[3], nullptr, bn0, tid, sm);
        gb_wait(tid, grp, GSZ * (++nb));

        pA = nA; pB = nB;
    }
}

// ---------------------------------------------------------------------------
// Orchestration: 3 launches on default stream (graph-capturable).
// ---------------------------------------------------------------------------
extern "C" void kernel_launch(void* const* d_in, const int* in_sizes, int n_in,
                              void* d_out, int out_size)
{
    (void)in_sizes; (void)n_in; (void)out_size;
    const float* x     = (const float*)d_in[0];
    const float* eWih0 = (const float*)d_in[2];
    const float* eWhh0 = (const float*)d_in[3];
    const float* ebih0 = (const float*)d_in[4];
    const float* ebhh0 = (const float*)d_in[5];
    const float* eWih1 = (const float*)d_in[6];
    const float* eWhh1 = (const float*)d_in[7];
    const float* ebih1 = (const float*)d_in[8];
    const float* ebhh1 = (const float*)d_in[9];
    const float* dWih0 = (const float*)d_in[10];
    const float* dWhh0 = (const float*)d_in[11];
    const float* dbih0 = (const float*)d_in[12];
    const float* dbhh0 = (const float*)d_in[13];
    const float* dWih1 = (const float*)d_in[14];
    const float* dWhh1 = (const float*)d_in[15];
    const float* dbih1 = (const float*)d_in[16];
    const float* dbhh1 = (const float*)d_in[17];
    const float* dWlin = (const float*)d_in[18];
    const float* dblin = (const float*)d_in[19];
    float* out = (float*)d_out;

    static bool s_attr = false;
    if (!s_attr) {
        cudaFuncSetAttribute(k_persist,
                             cudaFuncAttributeMaxDynamicSharedMemorySize, SMEM_BYTES);
        s_attr = true;
    }

    k_init<<<(BH + 255)/256, 256>>>(x);
    // order: eWhh0, eWih1, eWhh1, dWhh0, dWih1, dWhh1
    k_conv6<<<dim3(H_*H_/256, 6), 256>>>(eWhh0, eWih1, eWhh1, dWhh0, dWih1, dWhh1);
    k_persist<<<NCTA, THREADS, SMEM_BYTES>>>(x,
        eWih0, ebih0, ebhh0, ebih1, ebhh1,
        dWih0, dbih0, dbhh0, dbih1, dbhh1,
        dWlin, dblin, out);
}

// round 11
// speedup vs baseline: 1.8853x; 1.0251x over previous
#include <cuda_runtime.h>
#include <cuda_fp16.h>
#include <stdint.h>
#include <math.h>

// Problem dims (fixed)
#define B_ 256
#define S_ 256
#define I_ 3
#define H_ 1024
#define T_ 64
#define BH (B_*H_)

#define BM 64
#define BN 32
#define BK 64
#define KCH 16
#define NCTA 128
#define THREADS 256
#define GSZ 32            // CTAs per barrier group (one bm row-band)

// Shared memory layout (halves):
//  [0, 32768)        : cached W slice A (CW0: eWhh0 / dWhh1)   64 KB
//  [32768, 65536)    : cached W slice B (CW2: eWhh1)            64 KB
//  [65536, +4*SSTR)  : 4 pipeline stages (A0 8KB, A1 8KB, WS 4KB)
#define CW0_OFF 0
#define CW2_OFF 32768
#define STG_OFF 65536
#define O_A0 0
#define O_A1 4096
#define O_WS 8192
#define SSTR 10240
#define SMEM_BYTES ((STG_OFF + 4*SSTR)*2)   // 212992 B

// ---------------------------------------------------------------------------
// Device scratch (no allocation allowed)
// ---------------------------------------------------------------------------
__device__ __half g_y0[2*BH];
__device__ __half g_h1[2*BH];
__device__ __half g_hA[2*BH], g_hB[2*BH];
__device__ __half g_zb[BH];
__device__ float  g_inp[2*B_*I_];        // feedback ping-pong
// 0:eWhh0 1:eWih1 2:eWhh1 3:dWhh0 4:dWih1 5:dWhh1
__device__ __half g_W[6][H_*H_];
__device__ float  g_bs[4][H_];           // summed biases: enc0, enc1, dec0, dec1
__device__ unsigned g_cnt[4*32];         // per-band counters, padded

// ---------------------------------------------------------------------------
__global__ void k_init(const float* __restrict__ x,
                       const float* __restrict__ ebih0, const float* __restrict__ ebhh0,
                       const float* __restrict__ ebih1, const float* __restrict__ ebhh1,
                       const float* __restrict__ dbih0, const float* __restrict__ dbhh0,
                       const float* __restrict__ dbih1, const float* __restrict__ dbhh1) {
    int i = blockIdx.x * blockDim.x + threadIdx.x;
    if (i < 4) g_cnt[i*32] = 0;
    if (i < BH) g_zb[i] = __float2half(0.0f);
    if (i < B_*I_) {
        int b = i / I_, c = i % I_;
        g_inp[B_*I_ + i] = x[b*(S_*I_) + (S_-1)*I_ + c];   // slot 1 = initial
    }
    if (i < H_) {
        g_bs[0][i] = ebih0[i] + ebhh0[i];
        g_bs[1][i] = ebih1[i] + ebhh1[i];
        g_bs[2][i] = dbih0[i] + dbhh0[i];
        g_bs[3][i] = dbih1[i] + dbhh1[i];
    }
}

__global__ void k_conv6(const float* __restrict__ s0, const float* __restrict__ s1,
                        const float* __restrict__ s2, const float* __restrict__ s3,
                        const float* __restrict__ s4, const float* __restrict__ s5) {
    int i = blockIdx.x * blockDim.x + threadIdx.x;
    const float* srcs[6] = {s0, s1, s2, s3, s4, s5};
    int j = blockIdx.y;
    g_W[j][i] = __float2half(srcs[j][i]);
}

// ---------------------------------------------------------------------------
// Per-band (32-CTA) split barrier: monotonic counter, arrive early/wait late.
// ---------------------------------------------------------------------------
__device__ __forceinline__ void gb_arrive(int tid, int grp) {
    __syncthreads();
    if (tid == 0) { __threadfence(); atomicAdd(&g_cnt[grp*32], 1u); }
}
__device__ __forceinline__ void gb_wait(int tid, int grp, unsigned target) {
    if (tid == 0) {
        while (*(volatile unsigned*)&g_cnt[grp*32] < target) { }
        __threadfence();
    }
    __syncthreads();
}

__device__ __forceinline__ uint32_t smaddr(const void* p) {
    return (uint32_t)__cvta_generic_to_shared(p);
}
#define CP16(dst_sm, src_gm) \
    asm volatile("cp.async.cg.shared.global [%0], [%1], 16;\n" \
                 :: "r"(dst_sm), "l"(src_gm))
#define CPCOMMIT() asm volatile("cp.async.commit_group;")
#define CPWAIT2()  asm volatile("cp.async.wait_group 2;")

__device__ __forceinline__ float tanhA(float x) {
    float y; asm("tanh.approx.f32 %0, %1;" : "=f"(y) : "f"(x)); return y;
}

// Load this CTA's 32x1024 W slice into a smem cache region (16 chunks).
__device__ void loadWc(const __half* __restrict__ W, __half* Wc, int bn0, int tid) {
    const int lrow = tid >> 3, lcolh = (tid & 7) * 8;   // lrow 0..31
    const int sc = lcolh ^ ((lrow & 7) * 8);
    for (int kc = 0; kc < KCH; ++kc)
        CP16(smaddr(Wc + kc*2048 + lrow*64 + sc),
             W + (size_t)(bn0 + lrow)*H_ + kc*64 + lcolh);
    CPCOMMIT();
    asm volatile("cp.async.wait_group 0;");
    __syncthreads();
}

// Pre-barrier W-stream prefetch: chunks 0..2 into stages 0..2 (3 groups).
__device__ void preW3(const __half* __restrict__ Wst, int bn0, int tid, __half* sm) {
    __half* stg = sm + STG_OFF;
    const int lrow = tid >> 3, lcolh = (tid & 7) * 8;
    const int sc = lcolh ^ ((lrow & 7) * 8);
    #pragma unroll
    for (int c = 0; c < 3; ++c) {
        CP16(smaddr(stg + c*SSTR + O_WS + lrow*64 + sc),
             Wst + (size_t)(bn0 + lrow)*H_ + c*BK + lcolh);
        CPCOMMIT();
    }
}

// ldmatrix helpers (row width 64 halves, XOR swizzle on 8-half granule)
__device__ __forceinline__ void ldaW(uint32_t a[4], const __half* base, int kh, int lane, int wm) {
    int r  = wm*16 + (lane & 15);
    int cc = (kh + ((lane >> 4) * 8)) ^ ((r & 7) * 8);
    uint32_t addr = smaddr(base + r*64 + cc);
    asm volatile("ldmatrix.sync.aligned.m8n8.x4.shared.b16 {%0,%1,%2,%3}, [%4];"
        : "=r"(a[0]), "=r"(a[1]), "=r"(a[2]), "=r"(a[3]) : "r"(addr));
}
__device__ __forceinline__ void ldbW(uint32_t b[4], const __half* base, int kh, int lane, int wn) {
    int j  = lane >> 3;
    int r  = wn*16 + ((j >> 1) * 8) + (lane & 7);
    int cc = (kh + (j & 1) * 8) ^ ((r & 7) * 8);
    uint32_t addr = smaddr(base + r*64 + cc);
    asm volatile("ldmatrix.sync.aligned.m8n8.x4.shared.b16 {%0,%1,%2,%3}, [%4];"
        : "=r"(b[0]), "=r"(b[1]), "=r"(b[2]), "=r"(b[3]) : "r"(addr));
}
__device__ __forceinline__ void mma2(float acc[2][4], const uint32_t a[4], const uint32_t b[4]) {
    #pragma unroll
    for (int ni = 0; ni < 2; ++ni)
        asm volatile(
            "mma.sync.aligned.m16n8k16.row.col.f32.f16.f16.f32 "
            "{%0,%1,%2,%3}, {%4,%5,%6,%7}, {%8,%9}, {%0,%1,%2,%3};"
            : "+f"(acc[ni][0]), "+f"(acc[ni][1]), "+f"(acc[ni][2]), "+f"(acc[ni][3])
            : "r"(a[0]), "r"(a[1]), "r"(a[2]), "r"(a[3]),
              "r"(b[2*ni]), "r"(b[2*ni+1]));
}

// Epilogue: optional x-projection + summed bias, tanh(approx), fp16 write.
template<int APPROX>
__device__ __forceinline__ void epi(
    float acc[2][4],
    const float* __restrict__ xs, int xs_stride, const float* __restrict__ Wsm,
    const float* __restrict__ bs,
    __half* __restrict__ C,
    int bm0, int bn0, int lane, int wm, int wn)
{
    #pragma unroll
    for (int h = 0; h < 2; ++h) {
        const int row = bm0 + wm*16 + (lane >> 2) + h*8;
        float x0 = 0.f, x1 = 0.f, x2 = 0.f;
        if (xs) {
            const float* xr = xs + (size_t)row * xs_stride;
            x0 = xr[0]; x1 = xr[1]; x2 = xr[2];
        }
        #pragma unroll
        for (int ni = 0; ni < 2; ++ni) {
            const int col = bn0 + wn*16 + ni*8 + (lane & 3)*2;
            float v0 = acc[ni][h*2 + 0];
            float v1 = acc[ni][h*2 + 1];
            if (xs) {
                v0 += x0*Wsm[col*3+0] + x1*Wsm[col*3+1] + x2*Wsm[col*3+2];
                v1 += x0*Wsm[(col+1)*3+0] + x1*Wsm[(col+1)*3+1] + x2*Wsm[(col+1)*3+2];
            }
            v0 += bs[col];
            v1 += bs[col+1];
            if (APPROX) { v0 = tanhA(v0); v1 = tanhA(v1); }
            else        { v0 = tanhf(v0); v1 = tanhf(v1); }
            *(__half2*)(C + (size_t)row*H_ + col) =
                __halves2half2(__float2half(v0), __float2half(v1));
        }
    }
}

// ---------------------------------------------------------------------------
// Fused encoder interval t (entry: W1 chunks 0..2 pre-issued into stages 0..2):
//   ENC0: ys0[t]  = tanh(x[t]@Wih0 + Y@W0cached + b)        (acc0)
//   always: h1[.] = tanh(Y@W1stream + H@W2cached + b)       (acc1)
// ---------------------------------------------------------------------------
template<int ENC0>
__device__ void enc_step(int t,
    const __half* __restrict__ Y, const __half* __restrict__ Hp,
    const float* __restrict__ x, const float* __restrict__ eWih0,
    __half* __restrict__ Yout, __half* __restrict__ Hout,
    int bm0, int bn0, int tid, __half* sm)
{
    const int lane = tid & 31, wrp = tid >> 5, wm = wrp >> 1, wn = wrp & 1;
    const int lrow = tid >> 3, lcolh = (tid & 7) * 8;
    __half* stg = sm + STG_OFF;
    const __half* CW0 = sm + CW0_OFF;
    const __half* CW2 = sm + CW2_OFF;

    auto pfA = [&](int c, int slot) {
        __half* st = stg + slot*SSTR;
        const int k0 = c*BK;
        #pragma unroll
        for (int i = 0; i < 2; ++i) {
            int r  = lrow + 32*i;
            int sc = lcolh ^ ((r & 7) * 8);
            CP16(smaddr(st + O_A0 + r*64 + sc), Y  + (size_t)(bm0 + r)*H_ + k0 + lcolh);
            CP16(smaddr(st + O_A1 + r*64 + sc), Hp + (size_t)(bm0 + r)*H_ + k0 + lcolh);
        }
    };
    auto pfW = [&](int c, int slot) {
        __half* st = stg + slot*SSTR;
        const int k0 = c*BK;
        int sc = lcolh ^ ((lrow & 7) * 8);
        CP16(smaddr(st + O_WS + lrow*64 + sc), g_W[1] + (size_t)(bn0 + lrow)*H_ + k0 + lcolh);
    };

    pfA(0, 0); CPCOMMIT();
    pfA(1, 1); CPCOMMIT();
    pfA(2, 2); CPCOMMIT();

    float acc0[2][4] = {}, acc1[2][4] = {};
    for (int c = 0; c < KCH; ++c) {
        CPWAIT2();
        __syncthreads();
        if (c + 3 < KCH) { pfW(c + 3, (c + 3) & 3); pfA(c + 3, (c + 3) & 3); }
        CPCOMMIT();

        const __half* st = stg + (c & 3)*SSTR;
        #pragma unroll
        for (int k16 = 0; k16 < 4; ++k16) {
            const int kh = 16*k16;
            uint32_t ay[4];
            ldaW(ay, st + O_A0, kh, lane, wm);
            if (ENC0) {
                uint32_t bc[4];
                ldbW(bc, CW0 + c*2048, kh, lane, wn);
                mma2(acc0, ay, bc);
            }
            uint32_t b1w[4];
            ldbW(b1w, st + O_WS, kh, lane, wn);
            mma2(acc1, ay, b1w);
            uint32_t ah[4], b2w[4];
            ldaW(ah, st + O_A1, kh, lane, wm);
            ldbW(b2w, CW2 + c*2048, kh, lane, wn);
            mma2(acc1, ah, b2w);
        }
    }

    if (ENC0)
        epi<1>(acc0, x + t*I_, S_*I_, eWih0, g_bs[0], Yout, bm0, bn0, lane, wm, wn);
    epi<1>(acc1, nullptr, 0, nullptr, g_bs[1], Hout, bm0, bn0, lane, wm, wn);
}

// ---------------------------------------------------------------------------
// Decoder layer-0 interval (W3=dWhh0 streamed; entry: W3 chunks 0..2 staged):
//   hA = tanh(A0@W3 + inp@dWih0 + b); inp computed on the fly from out[:,t-1].
// ---------------------------------------------------------------------------
template<int FB>
__device__ void dec0(
    const __half* __restrict__ A0,
    const float* __restrict__ dWih0,
    const float* __restrict__ inp_prev, float* __restrict__ inp_cur,
    float* __restrict__ out, int t, const float* __restrict__ dblin,
    __half* __restrict__ Cout,
    int bm0, int bn0, int tid, __half* sm)
{
    const int lane = tid & 31, wrp = tid >> 5, wm = wrp >> 1, wn = wrp & 1;
    const int lrow = tid >> 3, lcolh = (tid & 7) * 8;
    __half* stg = sm + STG_OFF;

    auto pfA = [&](int c, int slot) {
        __half* st = stg + slot*SSTR;
        const int k0 = c*BK;
        #pragma unroll
        for (int i = 0; i < 2; ++i) {
            int r  = lrow + 32*i;
            int sc = lcolh ^ ((r & 7) * 8);
            CP16(smaddr(st + O_A0 + r*64 + sc), A0 + (size_t)(bm0 + r)*H_ + k0 + lcolh);
        }
    };
    auto pfW = [&](int c, int slot) {
        __half* st = stg + slot*SSTR;
        const int k0 = c*BK;
        int sc = lcolh ^ ((lrow & 7) * 8);
        CP16(smaddr(st + O_WS + lrow*64 + sc), g_W[3] + (size_t)(bn0 + lrow)*H_ + k0 + lcolh);
    };

    pfA(0, 0); CPCOMMIT();
    pfA(1, 1); CPCOMMIT();
    pfA(2, 2); CPCOMMIT();

    float acc[2][4] = {};
    for (int c = 0; c < KCH; ++c) {
        CPWAIT2();
        __syncthreads();
        if (c + 3 < KCH) { pfW(c + 3, (c + 3) & 3); pfA(c + 3, (c + 3) & 3); }
        CPCOMMIT();

        const __half* st = stg + (c & 3)*SSTR;
        #pragma unroll
        for (int k16 = 0; k16 < 4; ++k16) {
            const int kh = 16*k16;
            uint32_t a0[4], bA[4];
            ldaW(a0, st + O_A0, kh, lane, wm);
            ldbW(bA, st + O_WS, kh, lane, wn);
            mma2(acc, a0, bA);
        }
    }

    // Epilogue with on-the-fly feedback.
    #pragma unroll
    for (int h = 0; h < 2; ++h) {
        const int row = bm0 + wm*16 + (lane >> 2) + h*8;
        float c0, c1, c2;
        if (FB) {
            c0 = out[row*T_ + (t-1)];
            const float i0 = inp_prev[row*3 + 0];
            const float i1 = inp_prev[row*3 + 1];
            c1 = i0 - c0;
            c2 = i1 - c1;
        } else {
            c0 = inp_prev[row*3 + 0];
            c1 = inp_prev[row*3 + 1];
            c2 = inp_prev[row*3 + 2];
        }
        #pragma unroll
        for (int ni = 0; ni < 2; ++ni) {
            const int col = bn0 + wn*16 + ni*8 + (lane & 3)*2;
            float v0 = acc[ni][h*2 + 0];
            float v1 = acc[ni][h*2 + 1];
            v0 += c0*dWih0[col*3+0] + c1*dWih0[col*3+1] + c2*dWih0[col*3+2];
            v1 += c0*dWih0[(col+1)*3+0] + c1*dWih0[(col+1)*3+1] + c2*dWih0[(col+1)*3+2];
            v0 += g_bs[2][col];
            v1 += g_bs[2][col+1];
            v0 = tanhA(v0); v1 = tanhA(v1);
            *(__half2*)(Cout + (size_t)row*H_ + col) =
                __halves2half2(__float2half(v0), __float2half(v1));
        }
        if (bn0 == 0 && wn == 0 && (lane & 3) == 0) {
            inp_cur[row*3 + 0] = c0;
            inp_cur[row*3 + 1] = c1;
            inp_cur[row*3 + 2] = c2;
            out[row*T_ + t] = dblin[0];   // init for dec1's atomic partial dots
        }
    }
}

// ---------------------------------------------------------------------------
// Decoder layer-1 interval (W4=dWih1 streamed, W5=dWhh1 cached in CW0):
//   hB = tanh(A0@W4 + A1@W5c + b); fused decout: atomicAdd partial hB.Wlin.
// ---------------------------------------------------------------------------
__device__ void dec1(
    const __half* __restrict__ A0, const __half* __restrict__ A1,
    const float* __restrict__ Wlin,
    float* __restrict__ out, int t,
    __half* __restrict__ Cout,
    int bm0, int bn0, int tid, __half* sm)
{
    const int lane = tid & 31, wrp = tid >> 5, wm = wrp >> 1, wn = wrp & 1;
    const int lrow = tid >> 3, lcolh = (tid & 7) * 8;
    __half* stg = sm + STG_OFF;
    const __half* CW0 = sm + CW0_OFF;

    auto pfA = [&](int c, int slot) {
        __half* st = stg + slot*SSTR;
        const int k0 = c*BK;
        #pragma unroll
        for (int i = 0; i < 2; ++i) {
            int r  = lrow + 32*i;
            int sc = lcolh ^ ((r & 7) * 8);
            CP16(smaddr(st + O_A0 + r*64 + sc), A0 + (size_t)(bm0 + r)*H_ + k0 + lcolh);
            CP16(smaddr(st + O_A1 + r*64 + sc), A1 + (size_t)(bm0 + r)*H_ + k0 + lcolh);
        }
    };
    auto pfW = [&](int c, int slot) {
        __half* st = stg + slot*SSTR;
        const int k0 = c*BK;
        int sc = lcolh ^ ((lrow & 7) * 8);
        CP16(smaddr(st + O_WS + lrow*64 + sc), g_W[4] + (size_t)(bn0 + lrow)*H_ + k0 + lcolh);
    };

    pfA(0, 0); CPCOMMIT();
    pfA(1, 1); CPCOMMIT();
    pfA(2, 2); CPCOMMIT();

    float acc[2][4] = {};
    for (int c = 0; c < KCH; ++c) {
        CPWAIT2();
        __syncthreads();
        if (c + 3 < KCH) { pfW(c + 3, (c + 3) & 3); pfA(c + 3, (c + 3) & 3); }
        CPCOMMIT();

        const __half* st = stg + (c & 3)*SSTR;
        #pragma unroll
        for (int k16 = 0; k16 < 4; ++k16) {
            const int kh = 16*k16;
            uint32_t a0[4], bA[4];
            ldaW(a0, st + O_A0, kh, lane, wm);
            ldbW(bA, st + O_WS, kh, lane, wn);
            mma2(acc, a0, bA);
            uint32_t a1[4], bc[4];
            ldaW(a1, st + O_A1, kh, lane, wm);
            ldbW(bc, CW0 + c*2048, kh, lane, wn);
            mma2(acc, a1, bc);
        }
    }

    // Epilogue + fused decout partial dot (exact tanhf — feeds output directly).
    #pragma unroll
    for (int h = 0; h < 2; ++h) {
        const int row = bm0 + wm*16 + (lane >> 2) + h*8;
        float s = 0.0f;
        #pragma unroll
        for (int ni = 0; ni < 2; ++ni) {
            const int col = bn0 + wn*16 + ni*8 + (lane & 3)*2;
            float v0 = acc[ni][h*2 + 0] + g_bs[3][col];
            float v1 = acc[ni][h*2 + 1] + g_bs[3][col+1];
            v0 = tanhf(v0); v1 = tanhf(v1);
            *(__half2*)(Cout + (size_t)row*H_ + col) =
                __halves2half2(__float2half(v0), __float2half(v1));
            s += v0*Wlin[col] + v1*Wlin[col+1];
        }
        s += __shfl_xor_sync(0xffffffffu, s, 1);
        s += __shfl_xor_sync(0xffffffffu, s, 2);
        if ((lane & 3) == 0)
            atomicAdd(&out[row*T_ + t], s);
    }
}

// ---------------------------------------------------------------------------
// Persistent whole-network kernel. 128 CTAs x 256 threads, 1 CTA/SM.
// ---------------------------------------------------------------------------
__global__ __launch_bounds__(256) void k_persist(
    const float* __restrict__ x,
    const float* __restrict__ eWih0,
    const float* __restrict__ dWih0,
    const float* __restrict__ dWlin, const float* __restrict__ dblin,
    float* __restrict__ out)
{
    extern __shared__ __half sm[];
    const int tid = threadIdx.x;
    const int bid = blockIdx.x;
    const int bn0 = (bid & 31) * BN;
    const int bm0 = (bid >> 5) * BM;
    const int grp = bid >> 5;
    const int lane = tid & 31, wrp = tid >> 5, wm = wrp >> 1, wn = wrp & 1;
    unsigned nb = 0;

    // Cache W0 (eWhh0) and W2 (eWhh1) slices for the encoder phase.
    loadWc(g_W[0], sm + CW0_OFF, bn0, tid);
    loadWc(g_W[2], sm + CW2_OFF, bn0, tid);

    // t=0: ys0[0] = tanh(x[0]@Wih0 + b) — epilogue only (Y = 0).
    {
        float z[2][4] = {};
        epi<1>(z, x, S_*I_, eWih0, g_bs[0], g_y0, bm0, bn0, lane, wm, wn);
    }
    gb_arrive(tid, grp);
    preW3(g_W[1], bn0, tid, sm);
    gb_wait(tid, grp, GSZ * (++nb));

    // ---- Fused encoder: t = 1..255 (enc0[t] + enc1[t-1]) ----
    for (int t = 1; t < S_; ++t) {
        const __half* Y  = g_y0 + (size_t)((t-1)&1)*BH;
        const __half* Hp = (t >= 2) ? g_h1 + (size_t)((t-2)&1)*BH : g_zb;
        enc_step<1>(t, Y, Hp, x, eWih0,
                    g_y0 + (size_t)(t&1)*BH, g_h1 + (size_t)((t-1)&1)*BH,
                    bm0, bn0, tid, sm);
        gb_arrive(tid, grp);
        preW3(g_W[1], bn0, tid, sm);
        gb_wait(tid, grp, GSZ * (++nb));
    }
    // t = 256: enc1[255] only.
    enc_step<0>(S_, g_y0 + (size_t)((S_-1)&1)*BH, g_h1 + (size_t)((S_-2)&1)*BH,
                x, eWih0, g_y0, g_h1 + (size_t)((S_-1)&1)*BH, bm0, bn0, tid, sm);

    // Swap CW0 cache to W5 (dWhh1); prefetch W3 stream for dec0.
    gb_arrive(tid, grp);
    loadWc(g_W[5], sm + CW0_OFF, bn0, tid);
    preW3(g_W[3], bn0, tid, sm);
    gb_wait(tid, grp, GSZ * (++nb));

    // ---- Decoder: 2 barrier intervals per step ----
    const __half* pA = g_y0 + (size_t)((S_-1)&1)*BH;   // h_enc0
    const __half* pB = g_h1 + (size_t)((S_-1)&1)*BH;   // h_enc1
    for (int t = 0; t < T_; ++t) {
        __half* nA = g_hA + (size_t)(t&1)*BH;
        const float* inp_prev = g_inp + (size_t)((t-1)&1)*B_*I_;
        float* inp_cur = g_inp + (size_t)(t&1)*B_*I_;
        if (t == 0)
            dec0<0>(pA, dWih0, inp_prev, inp_cur, out, t, dblin, nA, bm0, bn0, tid, sm);
        else
            dec0<1>(pA, dWih0, inp_prev, inp_cur, out, t, dblin, nA, bm0, bn0, tid, sm);
        gb_arrive(tid, grp);
        preW3(g_W[4], bn0, tid, sm);
        gb_wait(tid, grp, GSZ * (++nb));

        __half* nB = g_hB + (size_t)(t&1)*BH;
        dec1(nA, pB, dWlin, out, t, nB, bm0, bn0, tid, sm);
        gb_arrive(tid, grp);
        if (t + 1 < T_) preW3(g_W[3], bn0, tid, sm);
        gb_wait(tid, grp, GSZ * (++nb));

        pA = nA; pB = nB;
    }
}

// ---------------------------------------------------------------------------
// Orchestration: 3 launches on default stream (graph-capturable).
// ---------------------------------------------------------------------------
extern "C" void kernel_launch(void* const* d_in, const int* in_sizes, int n_in,
                              void* d_out, int out_size)
{
    (void)in_sizes; (void)n_in; (void)out_size;
    const float* x     = (const float*)d_in[0];
    const float* eWih0 = (const float*)d_in[2];
    const float* eWhh0 = (const float*)d_in[3];
    const float* ebih0 = (const float*)d_in[4];
    const float* ebhh0 = (const float*)d_in[5];
    const float* eWih1 = (const float*)d_in[6];
    const float* eWhh1 = (const float*)d_in[7];
    const float* ebih1 = (const float*)d_in[8];
    const float* ebhh1 = (const float*)d_in[9];
    const float* dWih0 = (const float*)d_in[10];
    const float* dWhh0 = (const float*)d_in[11];
    const float* dbih0 = (const float*)d_in[12];
    const float* dbhh0 = (const float*)d_in[13];
    const float* dWih1 = (const float*)d_in[14];
    const float* dWhh1 = (const float*)d_in[15];
    const float* dbih1 = (const float*)d_in[16];
    const float* dbhh1 = (const float*)d_in[17];
    const float* dWlin = (const float*)d_in[18];
    const float* dblin = (const float*)d_in[19];
    float* out = (float*)d_out;

    static bool s_attr = false;
    if (!s_attr) {
        cudaFuncSetAttribute(k_persist,
                             cudaFuncAttributeMaxDynamicSharedMemorySize, SMEM_BYTES);
        s_attr = true;
    }

    k_init<<<(BH + 255)/256, 256>>>(x, ebih0, ebhh0, ebih1, ebhh1,
                                    dbih0, dbhh0, dbih1, dbhh1);
    // order: eWhh0, eWih1, eWhh1, dWhh0, dWih1, dWhh1
    k_conv6<<<dim3(H_*H_/256, 6), 256>>>(eWhh0, eWih1, eWhh1, dWhh0, dWih1, dWhh1);
    k_persist<<<NCTA, THREADS, SMEM_BYTES>>>(x, eWih0, dWih0, dWlin, dblin, out);
}